// round 1
// baseline (speedup 1.0000x reference)
#include <cuda_runtime.h>
#include <cstdint>

#define Hh 8
#define Bn 16
#define Ls 1024
#define Dm 512
#define DK 64
#define DV 64
#define M_ALL (Bn*Ls)              /* 16384 */
#define OUT_ELEMS (Bn*Ls*Dm)       /* 8388608 */
#define NROWS (Hh*Bn*Ls)           /* 131072 */

// ---------------- scratch (static device allocations; no cudaMalloc) ----------------
__device__ float g_qs[Hh*M_ALL*DK];        // 32 MB  [h][b*L+s][dk]
__device__ float g_ks[Hh*M_ALL*DK];        // 32 MB
__device__ float g_vs[Hh*M_ALL*DV];        // 32 MB
__device__ float g_headout[M_ALL*Hh*DV];   // 32 MB  [b*L+q][h*dv+e]
__device__ float g_projout[M_ALL*Dm];      // 32 MB
__device__ float g_p[NROWS];               // softmax max value (1/l)
__device__ int   g_amax[NROWS];            // argmax index

// ============================================================================
// Kernel 1: QKV projections.  For each (which in {q,k,v}, h):
//   C[h][m][e] = sum_d A[m][d] * W[h][d][e]     (M=16384, K=512, N=64)
// Tile: 128x64, 128 threads, 8x8 micro-tile, fp32.
// ============================================================================
__global__ __launch_bounds__(128) void proj_qkv_kernel(
    const float* __restrict__ qd, const float* __restrict__ kd, const float* __restrict__ vd,
    const float* __restrict__ wq, const float* __restrict__ wk, const float* __restrict__ wv)
{
    __shared__ float As[16][128];
    __shared__ float Bs[16][64];

    const int which = blockIdx.z >> 3;
    const int h     = blockIdx.z & 7;
    const float* A = (which == 0) ? qd : (which == 1) ? kd : vd;
    const float* W = ((which == 0) ? wq : (which == 1) ? wk : wv) + (size_t)h * Dm * DK;
    float* C = ((which == 0) ? g_qs : (which == 1) ? g_ks : g_vs) + (size_t)h * M_ALL * DK;

    const int m0  = blockIdx.x * 128;
    const int tid = threadIdx.x;
    const int ty  = tid >> 3;      // 0..15  (m groups of 8)
    const int tx  = tid & 7;       // 0..7   (n groups of 8)

    float acc[8][8];
#pragma unroll
    for (int i = 0; i < 8; i++)
#pragma unroll
        for (int j = 0; j < 8; j++) acc[i][j] = 0.f;

    const int arow = tid >> 2;           // 0..31
    const int ak   = (tid & 3) * 4;

    for (int k0 = 0; k0 < Dm; k0 += 16) {
        // A tile: 128 rows x 16 k, transposed into As[k][m]
#pragma unroll
        for (int p = 0; p < 4; p++) {
            int m = arow + p * 32;
            float4 v = *(const float4*)(A + (size_t)(m0 + m) * Dm + k0 + ak);
            As[ak + 0][m] = v.x; As[ak + 1][m] = v.y;
            As[ak + 2][m] = v.z; As[ak + 3][m] = v.w;
        }
        // W tile: 16 k x 64 n, direct copy (W is k-major)
#pragma unroll
        for (int p = 0; p < 2; p++) {
            int idx = tid + p * 128;            // 0..255
            int kk  = idx >> 4;
            int n4  = (idx & 15) * 4;
            *(float4*)&Bs[kk][n4] = *(const float4*)(W + (size_t)(k0 + kk) * DK + n4);
        }
        __syncthreads();
#pragma unroll
        for (int kk = 0; kk < 16; kk++) {
            float a[8], b[8];
            *(float4*)&a[0] = *(const float4*)&As[kk][ty * 8];
            *(float4*)&a[4] = *(const float4*)&As[kk][ty * 8 + 4];
            *(float4*)&b[0] = *(const float4*)&Bs[kk][tx * 8];
            *(float4*)&b[4] = *(const float4*)&Bs[kk][tx * 8 + 4];
#pragma unroll
            for (int i = 0; i < 8; i++)
#pragma unroll
                for (int j = 0; j < 8; j++) acc[i][j] += a[i] * b[j];
        }
        __syncthreads();
    }
#pragma unroll
    for (int i = 0; i < 8; i++) {
        int m = m0 + ty * 8 + i;
#pragma unroll
        for (int j = 0; j < 8; j += 4) {
            float4 v = make_float4(acc[i][j], acc[i][j + 1], acc[i][j + 2], acc[i][j + 3]);
            *(float4*)(C + (size_t)m * DK + tx * 8 + j) = v;
        }
    }
}

// ============================================================================
// Kernel 2: scores + online softmax stats (max, sum-exp, argmax). No dense
// score/softmax materialization. Block = (h, b, 64 q-rows); loops s in 128-tiles.
// 128 threads: ty 0..7 -> 8 q-rows each, tx 0..15 -> 8 s-cols each per tile.
// ============================================================================
__global__ __launch_bounds__(128) void attn_stats_kernel()
{
    __shared__ float Qst[64][64];    // [e][q]
    __shared__ float Kst[64][128];   // [e][s]

    const int h  = blockIdx.z;
    const int b  = blockIdx.y;
    const int q0 = blockIdx.x * 64;
    const float* Q  = g_qs + ((size_t)h * M_ALL + (size_t)b * Ls) * DK;
    const float* Kp = g_ks + ((size_t)h * M_ALL + (size_t)b * Ls) * DK;

    const int tid = threadIdx.x;
    const int ty  = tid >> 4;     // 0..7
    const int tx  = tid & 15;     // 0..15
    const float invT = 0.044194173824159216f;   // 1/sqrt(512)

    // load Q tile transposed
    {
        int r  = tid & 63;
        int c0 = tid >> 6;        // 0..1
#pragma unroll
        for (int p = 0; p < 8; p++) {
            int c = (c0 + p * 2) * 4;
            float4 v = *(const float4*)(Q + (size_t)(q0 + r) * DK + c);
            Qst[c + 0][r] = v.x; Qst[c + 1][r] = v.y;
            Qst[c + 2][r] = v.z; Qst[c + 3][r] = v.w;
        }
    }

    float m_[8], l_[8];
    int idx_[8];
#pragma unroll
    for (int i = 0; i < 8; i++) { m_[i] = -1e30f; l_[i] = 0.f; idx_[i] = 0; }

    for (int s0 = 0; s0 < Ls; s0 += 128) {
        __syncthreads();   // protect Kst from previous iteration readers
        {
            int s = tid;   // one s-row per thread
#pragma unroll
            for (int c4 = 0; c4 < 16; c4++) {
                float4 v = *(const float4*)(Kp + (size_t)(s0 + s) * DK + c4 * 4);
                Kst[c4 * 4 + 0][s] = v.x; Kst[c4 * 4 + 1][s] = v.y;
                Kst[c4 * 4 + 2][s] = v.z; Kst[c4 * 4 + 3][s] = v.w;
            }
        }
        __syncthreads();

        float acc[8][8];
#pragma unroll
        for (int i = 0; i < 8; i++)
#pragma unroll
            for (int j = 0; j < 8; j++) acc[i][j] = 0.f;

#pragma unroll
        for (int e = 0; e < 64; e++) {
            float a[8], bb[8];
            *(float4*)&a[0]  = *(const float4*)&Qst[e][ty * 8];
            *(float4*)&a[4]  = *(const float4*)&Qst[e][ty * 8 + 4];
            *(float4*)&bb[0] = *(const float4*)&Kst[e][tx * 8];
            *(float4*)&bb[4] = *(const float4*)&Kst[e][tx * 8 + 4];
#pragma unroll
            for (int i = 0; i < 8; i++)
#pragma unroll
                for (int j = 0; j < 8; j++) acc[i][j] += a[i] * bb[j];
        }

        // fold into online stats
#pragma unroll
        for (int i = 0; i < 8; i++) {
            float tm = acc[i][0]; int tj = 0;
#pragma unroll
            for (int j = 1; j < 8; j++) { if (acc[i][j] > tm) { tm = acc[i][j]; tj = j; } }
            float mo = m_[i];
            float mn = fmaxf(mo, tm);
            float s = 0.f;
#pragma unroll
            for (int j = 0; j < 8; j++) s += __expf((acc[i][j] - mn) * invT);
            l_[i] = l_[i] * __expf((mo - mn) * invT) + s;
            if (tm > mo) idx_[i] = s0 + tx * 8 + tj;
            m_[i] = mn;
        }
    }

    // reduce across the 16 tx lanes (half-warp segments)
#pragma unroll
    for (int i = 0; i < 8; i++) {
        float m = m_[i], l = l_[i];
        int id = idx_[i];
#pragma unroll
        for (int off = 8; off >= 1; off >>= 1) {
            float om = __shfl_xor_sync(0xffffffffu, m, off, 16);
            float ol = __shfl_xor_sync(0xffffffffu, l, off, 16);
            int   oi = __shfl_xor_sync(0xffffffffu, id, off, 16);
            if (om > m) { l = ol + l * __expf((m - om) * invT); m = om; id = oi; }
            else        { l = l + ol * __expf((om - m) * invT); }
        }
        if (tx == 0) {
            int row = (h * Bn + b) * Ls + q0 + ty * 8 + i;
            g_p[row]    = 1.0f / l;
            g_amax[row] = id;
        }
    }
}

// ============================================================================
// Kernel 3: scatter the single nonzero per attn row (after memset of region)
// ============================================================================
__global__ void scatter_kernel(float* __restrict__ attn)
{
    int r = blockIdx.x * blockDim.x + threadIdx.x;
    if (r >= NROWS) return;
    attn[(size_t)r * Ls + g_amax[r]] = g_p[r];
}

// ============================================================================
// Kernel 4: attn @ V collapsed to a gather:
//   headout[b*L+q][h*64+e] = p[h,b,q] * vs[h][b*L+argmax][e]
// ============================================================================
__global__ void gather_kernel()
{
    int idx = blockIdx.x * blockDim.x + threadIdx.x;
    if (idx >= M_ALL * Hh * DV) return;
    int e = idx & 63;
    int h = (idx >> 6) & 7;
    int m = idx >> 9;               // b*L + q
    int b = m >> 10;
    int row = (h * Bn + b) * Ls + (m & 1023);
    float p = g_p[row];
    int   s = g_amax[row];
    float v = g_vs[((size_t)h * M_ALL + (size_t)b * Ls + s) * DV + e];
    g_headout[idx] = p * v;
}

// ============================================================================
// Kernel 5: generic C = A @ B^T + bias with optional concatenated A.
//   A(m,k) = k < K1 ? A1[m][k] (lda=K1) : A2[m][k-K1] (lda=K-K1)
//   B is [N,K] row-major (so we compute A @ B^T), C is [M,N].
// Tile 128x128, 256 threads, 8x8 micro. mode 0: proj (A1=g_headout, C=g_projout)
//                                        mode 1: lin  (A1=ext q_data, A2=g_projout, C=ext)
// ============================================================================
__global__ __launch_bounds__(256) void gemm_bt_kernel(
    int mode, const float* __restrict__ Aext,
    const float* __restrict__ B, const float* __restrict__ bias,
    float* __restrict__ Cext, int K1, int K, int N)
{
    __shared__ float As[16][128];
    __shared__ float Bs[16][128];

    const float* A1 = (mode == 0) ? g_headout : Aext;
    const float* A2 = g_projout;
    float* C = (mode == 0) ? g_projout : Cext;

    const int m0  = blockIdx.y * 128;
    const int n0  = blockIdx.x * 128;
    const int tid = threadIdx.x;
    const int ty  = tid >> 4;    // 0..15
    const int tx  = tid & 15;    // 0..15

    float acc[8][8];
#pragma unroll
    for (int i = 0; i < 8; i++)
#pragma unroll
        for (int j = 0; j < 8; j++) acc[i][j] = 0.f;

    const int lrow = tid >> 2;          // 0..63
    const int lk   = (tid & 3) * 4;

    for (int k0 = 0; k0 < K; k0 += 16) {
        const float* Asrc; int lda, kc;
        if (k0 < K1) { Asrc = A1; lda = K1;      kc = k0; }
        else         { Asrc = A2; lda = K - K1;  kc = k0 - K1; }
#pragma unroll
        for (int p = 0; p < 2; p++) {
            int m = lrow + p * 64;
            float4 v = *(const float4*)(Asrc + (size_t)(m0 + m) * lda + kc + lk);
            As[lk + 0][m] = v.x; As[lk + 1][m] = v.y;
            As[lk + 2][m] = v.z; As[lk + 3][m] = v.w;
        }
#pragma unroll
        for (int p = 0; p < 2; p++) {
            int n = lrow + p * 64;
            float4 v = *(const float4*)(B + (size_t)(n0 + n) * K + k0 + lk);
            Bs[lk + 0][n] = v.x; Bs[lk + 1][n] = v.y;
            Bs[lk + 2][n] = v.z; Bs[lk + 3][n] = v.w;
        }
        __syncthreads();
#pragma unroll
        for (int kk = 0; kk < 16; kk++) {
            float a[8], bb[8];
            *(float4*)&a[0]  = *(const float4*)&As[kk][ty * 8];
            *(float4*)&a[4]  = *(const float4*)&As[kk][ty * 8 + 4];
            *(float4*)&bb[0] = *(const float4*)&Bs[kk][tx * 8];
            *(float4*)&bb[4] = *(const float4*)&Bs[kk][tx * 8 + 4];
#pragma unroll
            for (int i = 0; i < 8; i++)
#pragma unroll
                for (int j = 0; j < 8; j++) acc[i][j] += a[i] * bb[j];
        }
        __syncthreads();
    }

#pragma unroll
    for (int i = 0; i < 8; i++) {
        int m = m0 + ty * 8 + i;
#pragma unroll
        for (int j = 0; j < 8; j++) {
            int n = n0 + tx * 8 + j;
            C[(size_t)m * N + n] = acc[i][j] + bias[n];
        }
    }
}

// ============================================================================
extern "C" void kernel_launch(void* const* d_in, const int* in_sizes, int n_in,
                              void* d_out, int out_size)
{
    const float* q_data = (const float*)d_in[0];
    const float* k_data = (const float*)d_in[1];
    const float* v_data = (const float*)d_in[2];
    const float* w_qs   = (const float*)d_in[3];
    const float* w_ks   = (const float*)d_in[4];
    const float* w_vs   = (const float*)d_in[5];
    const float* proj_w = (const float*)d_in[6];
    const float* proj_b = (const float*)d_in[7];
    const float* lin_w  = (const float*)d_in[8];
    const float* lin_b  = (const float*)d_in[9];

    float* out  = (float*)d_out;                    // [B, L, D]
    float* attn = out + OUT_ELEMS;                  // [H*B, L, L]

    // 1) per-head QKV projections
    proj_qkv_kernel<<<dim3(M_ALL / 128, 1, 24), 128>>>(q_data, k_data, v_data,
                                                       w_qs, w_ks, w_vs);
    // 2) scores + online softmax stats (no dense softmax)
    attn_stats_kernel<<<dim3(Ls / 64, Bn, Hh), 128>>>();

    // 3) dense attn output = zeros + one nonzero per row
    cudaMemsetAsync(attn, 0, (size_t)NROWS * Ls * sizeof(float));
    scatter_kernel<<<(NROWS + 255) / 256, 256>>>(attn);

    // 4) attn @ V as a gather
    gather_kernel<<<(M_ALL * Hh * DV + 255) / 256, 256>>>();

    // 5) output projection: projout = headout @ proj_w^T + proj_b
    gemm_bt_kernel<<<dim3(Dm / 128, M_ALL / 128), 256>>>(
        0, nullptr, proj_w, proj_b, nullptr, Dm, Dm, Dm);

    // 6) final linear: out = [q_data | projout] @ lin_w^T + lin_b
    gemm_bt_kernel<<<dim3(Dm / 128, M_ALL / 128), 256>>>(
        1, q_data, lin_w, lin_b, out, Dm, 2 * Dm, Dm);
}

// round 3
// speedup vs baseline: 1.2963x; 1.2963x over previous
#include <cuda_runtime.h>
#include <cstdint>

#define Hh 8
#define Bn 16
#define Ls 1024
#define Dm 512
#define M_ALL (Bn*Ls)              /* 16384 */
#define OUT_ELEMS (Bn*Ls*Dm)       /* 8388608 */
#define NROWS (Hh*Bn*Ls)           /* 131072 */
#define INVT 0.044194173824159216f /* 1/sqrt(512) */

// ---------------- static device scratch ----------------
__device__ float g_qs[M_ALL*Dm];        // [m][h*64+e]
__device__ float g_ks[M_ALL*Dm];
__device__ float g_vs[M_ALL*Dm];
__device__ float g_headout[M_ALL*Dm];   // [m][h*64+e]
__device__ float g_projout[M_ALL*Dm];
__device__ float g_wt[3*Dm*Dm];         // transposed qkv weights: [w][n=h*64+e][k=d]
__device__ float g_p[NROWS];
__device__ int   g_amax[NROWS];

// ---------------- helpers ----------------
__device__ __forceinline__ uint32_t smem_u32(const void* p) {
    uint32_t a;
    asm("{ .reg .u64 t; cvta.to.shared.u64 t, %1; cvt.u32.u64 %0, t; }" : "=r"(a) : "l"(p));
    return a;
}
__device__ __forceinline__ void cp_async16(void* sdst, const void* gsrc) {
    uint32_t s = smem_u32(sdst);
    asm volatile("cp.async.ca.shared.global [%0], [%1], 16;" :: "r"(s), "l"(gsrc));
}
#define CP_COMMIT() asm volatile("cp.async.commit_group;" ::: "memory")
#define CP_WAIT1()  asm volatile("cp.async.wait_group 1;" ::: "memory")
#define CP_WAIT0()  asm volatile("cp.async.wait_group 0;" ::: "memory")

// split fp32 -> tf32 hi + tf32 lo (2-way split; 3 cross products ~= 21-bit product)
__device__ __forceinline__ void splitf(float x, uint32_t& hi, uint32_t& lo) {
    uint32_t h;
    asm("cvt.rna.tf32.f32 %0, %1;" : "=r"(h) : "f"(x));
    float l = x - __uint_as_float(h);
    uint32_t lw;
    asm("cvt.rna.tf32.f32 %0, %1;" : "=r"(lw) : "f"(l));
    hi = h; lo = lw;
}
__device__ __forceinline__ void mma8(float* d, const uint32_t* a, const uint32_t* b) {
    asm volatile("mma.sync.aligned.m16n8k8.row.col.f32.tf32.tf32.f32 "
                 "{%0,%1,%2,%3}, {%4,%5,%6,%7}, {%8,%9}, {%0,%1,%2,%3};"
                 : "+f"(d[0]), "+f"(d[1]), "+f"(d[2]), "+f"(d[3])
                 : "r"(a[0]), "r"(a[1]), "r"(a[2]), "r"(a[3]),
                   "r"(b[0]), "r"(b[1]));
}
// fast exp via exp2 polynomial (FMA pipe only, ~2e-6 rel err); arg <= 0
__device__ __forceinline__ float fexp(float t) {
    float z = t * 1.4426950408889634f;
    z = fmaxf(z, -120.f);
    int   e  = __float2int_rn(z);
    float f  = z - (float)e;                 // [-0.5, 0.5]
    float p = 1.3333558146428443e-3f;
    p = fmaf(p, f, 9.6181291976233960e-3f);
    p = fmaf(p, f, 5.5504108664821580e-2f);
    p = fmaf(p, f, 2.4022650695910071e-1f);
    p = fmaf(p, f, 6.9314718055994531e-1f);
    p = fmaf(p, f, 1.0f);
    return __int_as_float(__float_as_int(p) + (e << 23));
}

// ============================================================================
// GEMM: C[M][Dm] = concat(A1|A2)[M][K] @ Bm[Dm rows][K]^T (+bias)
// 128x128 CTA tile, 256 thr, 8 warps as 2(M)x4(N), warp tile 64x32.
// K streamed in 32-chunks via cp.async double buffer. tf32 3-product MMA.
// smem: As[2][128][36], Bs[2][128][36] fp32 (split done in registers)
// ============================================================================
#define GPAD 36
#define G_SMEM (4*128*GPAD*4)   /* 73728 */
__global__ __launch_bounds__(256) void gemm_mma(
    const float* __restrict__ A1, const float* __restrict__ A2, int K1, int K,
    const float* __restrict__ Bm, const float* __restrict__ bias, float* __restrict__ C)
{
    extern __shared__ float sm[];
    float* Abuf[2] = { sm,              sm + 128*GPAD };
    float* Bbuf[2] = { sm + 2*128*GPAD, sm + 3*128*GPAD };

    const int tid = threadIdx.x;
    const int m0 = blockIdx.y * 128, n0 = blockIdx.x * 128;
    const int wid = tid >> 5, lane = tid & 31;
    const int wm = wid & 1, wn = wid >> 1;
    const int lr = lane >> 2, lc = lane & 3;

    const int NC = K / 32;

#define G_LOAD(buf, k0_) do {                                                   \
        int k0 = (k0_);                                                         \
        const float* Asrc; int lda, kc;                                         \
        if (k0 < K1) { Asrc = A1; lda = K1;     kc = k0; }                      \
        else         { Asrc = A2; lda = K - K1; kc = k0 - K1; }                 \
        _Pragma("unroll")                                                       \
        for (int i = 0; i < 4; i++) {                                           \
            int id = tid + i * 256;                                             \
            int row = id >> 3, c4 = (id & 7) * 4;                               \
            cp_async16(Abuf[buf] + row*GPAD + c4,                               \
                       Asrc + (size_t)(m0 + row)*lda + kc + c4);                \
        }                                                                       \
        _Pragma("unroll")                                                       \
        for (int i = 0; i < 4; i++) {                                           \
            int id = tid + i * 256;                                             \
            int row = id >> 3, c4 = (id & 7) * 4;                               \
            cp_async16(Bbuf[buf] + row*GPAD + c4,                               \
                       Bm + (size_t)(n0 + row)*K + k0 + c4);                    \
        }                                                                       \
    } while (0)

    G_LOAD(0, 0); CP_COMMIT();
    G_LOAD(1, 32); CP_COMMIT();

    float acc[4][4][4];
#pragma unroll
    for (int a = 0; a < 4; a++)
#pragma unroll
        for (int b = 0; b < 4; b++)
#pragma unroll
            for (int c = 0; c < 4; c++) acc[a][b][c] = 0.f;

    for (int c = 0; c < NC; c++) {
        if (c < NC - 1) CP_WAIT1(); else CP_WAIT0();
        __syncthreads();
        const int buf = c & 1;
        const float* Ab = Abuf[buf] + wm * 64 * GPAD;
        const float* Bb = Bbuf[buf] + wn * 32 * GPAD;
#pragma unroll
        for (int ks = 0; ks < 4; ks++) {
            const int kb = ks * 8 + lc;
            uint32_t bh[4][2], bl[4][2];
#pragma unroll
            for (int nt = 0; nt < 4; nt++) {
                splitf(Bb[(nt*8 + lr)*GPAD + kb],     bh[nt][0], bl[nt][0]);
                splitf(Bb[(nt*8 + lr)*GPAD + kb + 4], bh[nt][1], bl[nt][1]);
            }
#pragma unroll
            for (int mt = 0; mt < 4; mt++) {
                uint32_t ah[4], al[4];
                splitf(Ab[(mt*16 + lr    )*GPAD + kb],     ah[0], al[0]);
                splitf(Ab[(mt*16 + lr + 8)*GPAD + kb],     ah[1], al[1]);
                splitf(Ab[(mt*16 + lr    )*GPAD + kb + 4], ah[2], al[2]);
                splitf(Ab[(mt*16 + lr + 8)*GPAD + kb + 4], ah[3], al[3]);
#pragma unroll
                for (int nt = 0; nt < 4; nt++) {
                    mma8(acc[mt][nt], ah, bh[nt]);
                    mma8(acc[mt][nt], ah, bl[nt]);
                    mma8(acc[mt][nt], al, bh[nt]);
                }
            }
        }
        __syncthreads();
        if (c + 2 < NC) { G_LOAD(buf, (c + 2) * 32); CP_COMMIT(); }
    }

    // epilogue
#pragma unroll
    for (int mt = 0; mt < 4; mt++) {
#pragma unroll
        for (int nt = 0; nt < 4; nt++) {
            int row = m0 + wm*64 + mt*16 + lr;
            int col = n0 + wn*32 + nt*8 + 2*lc;
            float bx = 0.f, by = 0.f;
            if (bias) { bx = bias[col]; by = bias[col + 1]; }
            *(float2*)(C + (size_t)row * Dm + col) =
                make_float2(acc[mt][nt][0] + bx, acc[mt][nt][1] + by);
            *(float2*)(C + (size_t)(row + 8) * Dm + col) =
                make_float2(acc[mt][nt][2] + bx, acc[mt][nt][3] + by);
        }
    }
#undef G_LOAD
}

// ============================================================================
// QK^T + online softmax stats. CTA = (h, b, 128 q rows); streams 8 K-tiles
// of 128 rows. Scores stay in MMA fragments; per-thread online
// max/argmax/sumexp, then lane-quad shfl reduce + smem cross-warp reduce.
// smem: Qs[128][68], Ks[2][128][68], red arrays.
// ============================================================================
#define APAD 68
#define S_SMEM (3*128*APAD*4 + 512*4*3)  /* 104448 + 6144 = 110592 */
__global__ __launch_bounds__(256) void attn_stats_mma()
{
    extern __shared__ float sm[];
    float* Qs   = sm;
    float* Kbuf[2] = { sm + 128*APAD, sm + 2*128*APAD };
    float* redm = sm + 3*128*APAD;
    float* redl = redm + 512;
    int*   redi = (int*)(redl + 512);

    const int tid = threadIdx.x;
    const int h = blockIdx.z, b = blockIdx.y, q0 = blockIdx.x * 128;
    const int wid = tid >> 5, lane = tid & 31;
    const int wm = wid & 1, wn = wid >> 1;
    const int lr = lane >> 2, lc = lane & 3;

    const float* Qg = g_qs + ((size_t)(b * Ls + q0)) * Dm + h * 64;
    const float* Kg = g_ks + ((size_t)(b * Ls)) * Dm + h * 64;

    // Q tile: 128 rows x 64 floats
#pragma unroll
    for (int i = 0; i < 8; i++) {
        int id = tid + i * 256;
        int row = id >> 4, c4 = (id & 15) * 4;
        cp_async16(Qs + row*APAD + c4, Qg + (size_t)row * Dm + c4);
    }
    CP_COMMIT();

#define K_LOAD(buf, t_) do {                                                    \
        _Pragma("unroll")                                                       \
        for (int i = 0; i < 8; i++) {                                           \
            int id = tid + i * 256;                                             \
            int row = id >> 4, c4 = (id & 15) * 4;                              \
            cp_async16(Kbuf[buf] + row*APAD + c4,                               \
                       Kg + (size_t)((t_)*128 + row) * Dm + c4);                \
        }                                                                       \
    } while (0)

    K_LOAD(0, 0); CP_COMMIT();
    K_LOAD(1, 1); CP_COMMIT();

    float rm[8], rl[8];
    int ridx[8];
#pragma unroll
    for (int i = 0; i < 8; i++) { rm[i] = -1e30f; rl[i] = 0.f; ridx[i] = 0; }

    for (int t = 0; t < 8; t++) {
        if (t < 7) CP_WAIT1(); else CP_WAIT0();
        __syncthreads();
        const int buf = t & 1;
        const float* Ab = Qs + wm * 64 * APAD;
        const float* Bb = Kbuf[buf] + wn * 32 * APAD;

        float acc[4][4][4];
#pragma unroll
        for (int a = 0; a < 4; a++)
#pragma unroll
            for (int bb = 0; bb < 4; bb++)
#pragma unroll
                for (int cc = 0; cc < 4; cc++) acc[a][bb][cc] = 0.f;

#pragma unroll
        for (int ks = 0; ks < 8; ks++) {
            const int kb = ks * 8 + lc;
            uint32_t bh[4][2], bl[4][2];
#pragma unroll
            for (int nt = 0; nt < 4; nt++) {
                splitf(Bb[(nt*8 + lr)*APAD + kb],     bh[nt][0], bl[nt][0]);
                splitf(Bb[(nt*8 + lr)*APAD + kb + 4], bh[nt][1], bl[nt][1]);
            }
#pragma unroll
            for (int mt = 0; mt < 4; mt++) {
                uint32_t ah[4], al[4];
                splitf(Ab[(mt*16 + lr    )*APAD + kb],     ah[0], al[0]);
                splitf(Ab[(mt*16 + lr + 8)*APAD + kb],     ah[1], al[1]);
                splitf(Ab[(mt*16 + lr    )*APAD + kb + 4], ah[2], al[2]);
                splitf(Ab[(mt*16 + lr + 8)*APAD + kb + 4], ah[3], al[3]);
#pragma unroll
                for (int nt = 0; nt < 4; nt++) {
                    mma8(acc[mt][nt], ah, bh[nt]);
                    mma8(acc[mt][nt], ah, bl[nt]);
                    mma8(acc[mt][nt], al, bh[nt]);
                }
            }
        }

        // fold tile into per-thread online stats
        const int s0 = t * 128;
#pragma unroll
        for (int mt = 0; mt < 4; mt++) {
#pragma unroll
            for (int half = 0; half < 2; half++) {
                const int r8 = mt * 2 + half;
                float lm = -1e30f; int li = 0;
#pragma unroll
                for (int nt = 0; nt < 4; nt++) {
#pragma unroll
                    for (int j = 0; j < 2; j++) {
                        float v = acc[mt][nt][half*2 + j];
                        int cl = wn*32 + nt*8 + 2*lc + j;
                        if (v > lm) { lm = v; li = cl; }
                    }
                }
                float nm = fmaxf(rm[r8], lm);
                float add = 0.f;
#pragma unroll
                for (int nt = 0; nt < 4; nt++) {
#pragma unroll
                    for (int j = 0; j < 2; j++)
                        add += fexp((acc[mt][nt][half*2 + j] - nm) * INVT);
                }
                rl[r8] = rl[r8] * fexp((rm[r8] - nm) * INVT) + add;
                if (lm > rm[r8]) ridx[r8] = s0 + li;
                rm[r8] = nm;
            }
        }
        __syncthreads();
        if (t + 2 < 8) { K_LOAD(buf, t + 2); CP_COMMIT(); }
    }

    // reduce across the 4 lanes of each quad (same rows, different cols)
#pragma unroll
    for (int r8 = 0; r8 < 8; r8++) {
        float m = rm[r8], l = rl[r8];
        int id = ridx[r8];
#pragma unroll
        for (int off = 1; off <= 2; off <<= 1) {
            float om = __shfl_xor_sync(0xffffffffu, m, off);
            float ol = __shfl_xor_sync(0xffffffffu, l, off);
            int   oi = __shfl_xor_sync(0xffffffffu, id, off);
            if (om > m) { l = ol + l * fexp((m - om) * INVT); m = om; id = oi; }
            else        { l = l + ol * fexp((om - m) * INVT); }
        }
        if (lc == 0) {
            int rowl = wm*64 + (r8 >> 1)*16 + (r8 & 1)*8 + lr;
            redm[rowl*4 + wn] = m;
            redl[rowl*4 + wn] = l;
            redi[rowl*4 + wn] = id;
        }
    }
    __syncthreads();

    if (tid < 128) {
        float m = redm[tid*4], l = redl[tid*4];
        int id = redi[tid*4];
#pragma unroll
        for (int w = 1; w < 4; w++) {
            float om = redm[tid*4 + w], ol = redl[tid*4 + w];
            int   oi = redi[tid*4 + w];
            if (om > m) { l = ol + l * fexp((m - om) * INVT); m = om; id = oi; }
            else        { l = l + ol * fexp((om - m) * INVT); }
        }
        int row = (h * Bn + b) * Ls + q0 + tid;
        g_p[row] = 1.0f / l;
        g_amax[row] = id;
    }
#undef K_LOAD
}

// ============================================================================
// small kernels
// ============================================================================
__global__ void wt_prep(const float* __restrict__ wq, const float* __restrict__ wk,
                        const float* __restrict__ wv)
{
    int idx = blockIdx.x * 256 + threadIdx.x;
    if (idx >= 3 * 8 * 512 * 16) return;
    int e4 = idx & 15;
    int d  = (idx >> 4) & 511;
    int h  = (idx >> 13) & 7;
    int w  = idx >> 16;
    const float* W = ((w == 0) ? wq : (w == 1) ? wk : wv) + (size_t)h * Dm * 64;
    float4 v = *(const float4*)(W + d * 64 + e4 * 4);
    float* WT = g_wt + (size_t)w * Dm * Dm;
    int n = h * 64 + e4 * 4;
    WT[(size_t)(n + 0) * Dm + d] = v.x;
    WT[(size_t)(n + 1) * Dm + d] = v.y;
    WT[(size_t)(n + 2) * Dm + d] = v.z;
    WT[(size_t)(n + 3) * Dm + d] = v.w;
}

__global__ void scatter_kernel(float* __restrict__ attn)
{
    int r = blockIdx.x * blockDim.x + threadIdx.x;
    if (r >= NROWS) return;
    attn[(size_t)r * Ls + g_amax[r]] = g_p[r];
}

__global__ void gather_kernel()
{
    int idx = blockIdx.x * blockDim.x + threadIdx.x;
    if (idx >= M_ALL * Dm) return;
    int e = idx & 63;
    int h = (idx >> 6) & 7;
    int m = idx >> 9;               // b*L + q
    int b = m >> 10;
    int q = m & 1023;
    int row = (h * Bn + b) * Ls + q;
    float p = g_p[row];
    int   s = g_amax[row];
    g_headout[idx] = p * g_vs[((size_t)(b * Ls + s)) * Dm + h * 64 + e];
}

// ============================================================================
extern "C" void kernel_launch(void* const* d_in, const int* in_sizes, int n_in,
                              void* d_out, int out_size)
{
    const float* q_data = (const float*)d_in[0];
    const float* k_data = (const float*)d_in[1];
    const float* v_data = (const float*)d_in[2];
    const float* w_qs   = (const float*)d_in[3];
    const float* w_ks   = (const float*)d_in[4];
    const float* w_vs   = (const float*)d_in[5];
    const float* proj_w = (const float*)d_in[6];
    const float* proj_b = (const float*)d_in[7];
    const float* lin_w  = (const float*)d_in[8];
    const float* lin_b  = (const float*)d_in[9];

    float* out  = (float*)d_out;                    // [B, L, D]
    float* attn = out + OUT_ELEMS;                  // [H*B, L, L]

    float *p_qs, *p_ks, *p_vs, *p_ho, *p_po, *p_wt;
    cudaGetSymbolAddress((void**)&p_qs, g_qs);
    cudaGetSymbolAddress((void**)&p_ks, g_ks);
    cudaGetSymbolAddress((void**)&p_vs, g_vs);
    cudaGetSymbolAddress((void**)&p_ho, g_headout);
    cudaGetSymbolAddress((void**)&p_po, g_projout);
    cudaGetSymbolAddress((void**)&p_wt, g_wt);

    cudaFuncSetAttribute(gemm_mma, cudaFuncAttributeMaxDynamicSharedMemorySize, G_SMEM);
    cudaFuncSetAttribute(attn_stats_mma, cudaFuncAttributeMaxDynamicSharedMemorySize, S_SMEM);

    // 0) transpose qkv weights into [n][k] form
    wt_prep<<<768, 256>>>(w_qs, w_ks, w_vs);

    // 1) QKV projections (tensor cores, tf32 3-product)
    gemm_mma<<<dim3(4, 128), 256, G_SMEM>>>(q_data, q_data, Dm, Dm, p_wt,               nullptr, p_qs);
    gemm_mma<<<dim3(4, 128), 256, G_SMEM>>>(k_data, k_data, Dm, Dm, p_wt + Dm*Dm,       nullptr, p_ks);
    gemm_mma<<<dim3(4, 128), 256, G_SMEM>>>(v_data, v_data, Dm, Dm, p_wt + 2*Dm*Dm,     nullptr, p_vs);

    // 2) QK^T + softmax stats (fused, no dense scores)
    attn_stats_mma<<<dim3(8, 16, 8), 256, S_SMEM>>>();

    // 3) dense attn output: zeros + single nonzero per row
    cudaMemsetAsync(attn, 0, (size_t)NROWS * Ls * sizeof(float));
    scatter_kernel<<<(NROWS + 255) / 256, 256>>>(attn);

    // 4) attn @ V collapsed to gather
    gather_kernel<<<(M_ALL * Dm + 255) / 256, 256>>>();

    // 5) output projection
    gemm_mma<<<dim3(4, 128), 256, G_SMEM>>>(p_ho, p_ho, Dm, Dm, proj_w, proj_b, p_po);

    // 6) final linear: out = [q_data | projout] @ lin_w^T + lin_b
    gemm_mma<<<dim3(4, 128), 256, G_SMEM>>>(q_data, p_po, Dm, 2*Dm, lin_w, lin_b, out);
}

// round 4
// speedup vs baseline: 1.5061x; 1.1618x over previous
#include <cuda_runtime.h>
#include <cstdint>

#define Hh 8
#define Bn 16
#define Ls 1024
#define Dm 512
#define M_ALL (Bn*Ls)              /* 16384 */
#define OUT_ELEMS (Bn*Ls*Dm)       /* 8388608 */
#define NROWS (Hh*Bn*Ls)           /* 131072 */
#define INVT 0.044194173824159216f /* 1/sqrt(512) */

// ---------------- static device scratch ----------------
__device__ float g_qs[M_ALL*Dm];        // [m][h*64+e]
__device__ float g_ks[M_ALL*Dm];
__device__ float g_vs[M_ALL*Dm];
__device__ float g_headout[M_ALL*Dm];   // [m][h*64+e]
__device__ float g_projout[M_ALL*Dm];
__device__ float g_wt[3*Dm*Dm];         // transposed qkv weights: [w][n=h*64+e][k=d]
__device__ float g_p[NROWS];
__device__ int   g_amax[NROWS];

// ---------------- helpers ----------------
__device__ __forceinline__ uint32_t smem_u32(const void* p) {
    uint32_t a;
    asm("{ .reg .u64 t; cvta.to.shared.u64 t, %1; cvt.u32.u64 %0, t; }" : "=r"(a) : "l"(p));
    return a;
}
__device__ __forceinline__ void cp_async16(void* sdst, const void* gsrc) {
    uint32_t s = smem_u32(sdst);
    asm volatile("cp.async.ca.shared.global [%0], [%1], 16;" :: "r"(s), "l"(gsrc));
}
#define CP_COMMIT() asm volatile("cp.async.commit_group;" ::: "memory")
#define CP_WAIT1()  asm volatile("cp.async.wait_group 1;" ::: "memory")
#define CP_WAIT0()  asm volatile("cp.async.wait_group 0;" ::: "memory")

// fp32 -> tf32 hi (rounded) + raw fp32 residual (exact; HMMA truncates it to
// tf32 internally, losing only ~2^-24-scale info). 2 ops instead of 3.
__device__ __forceinline__ void splitf(float x, uint32_t& hi, uint32_t& lo) {
    uint32_t h;
    asm("cvt.rna.tf32.f32 %0, %1;" : "=r"(h) : "f"(x));
    hi = h;
    lo = __float_as_uint(x - __uint_as_float(h));
}
__device__ __forceinline__ void mma8(float* d, const uint32_t* a, const uint32_t* b) {
    asm volatile("mma.sync.aligned.m16n8k8.row.col.f32.tf32.tf32.f32 "
                 "{%0,%1,%2,%3}, {%4,%5,%6,%7}, {%8,%9}, {%0,%1,%2,%3};"
                 : "+f"(d[0]), "+f"(d[1]), "+f"(d[2]), "+f"(d[3])
                 : "r"(a[0]), "r"(a[1]), "r"(a[2]), "r"(a[3]),
                   "r"(b[0]), "r"(b[1]));
}
// fast exp via exp2 polynomial (FMA pipe only, ~2e-6 rel err)
__device__ __forceinline__ float fexp(float t) {
    float z = t * 1.4426950408889634f;
    z = fmaxf(z, -120.f);
    int   e  = __float2int_rn(z);
    float f  = z - (float)e;                 // [-0.5, 0.5]
    float p = 1.3333558146428443e-3f;
    p = fmaf(p, f, 9.6181291976233960e-3f);
    p = fmaf(p, f, 5.5504108664821580e-2f);
    p = fmaf(p, f, 2.4022650695910071e-1f);
    p = fmaf(p, f, 6.9314718055994531e-1f);
    p = fmaf(p, f, 1.0f);
    return __int_as_float(__float_as_int(p) + (e << 23));
}

// ============================================================================
// GEMM core: C[128 x 64 tile] over C = concat(A1|A2)[M][K] @ Bm[N][K]^T (+bias)
// 128 threads = 4 warps as 2(M)x2(N); warp tile 64x32; K chunks of 32,
// cp.async double buffer. tf32 3-product MMA. 3 CTAs/SM.
// smem: A[2][128][36] + B[2][64][36] fp32 = 55296 B
// ============================================================================
#define GPAD 36
#define G_SMEM ((2*128*GPAD + 2*64*GPAD)*4)   /* 55296 */

__device__ __forceinline__ void gemm_core(
    const float* __restrict__ A1, const float* __restrict__ A2, int K1, int K,
    const float* __restrict__ Bm, const float* __restrict__ bias,
    float* __restrict__ C, int m0, int n0, float* sm)
{
    float* Abuf[2] = { sm,              sm + 128*GPAD };
    float* Bbuf[2] = { sm + 2*128*GPAD, sm + 2*128*GPAD + 64*GPAD };

    const int tid = threadIdx.x;
    const int wid = tid >> 5, lane = tid & 31;
    const int wm = wid & 1, wn = wid >> 1;
    const int lr = lane >> 2, lc = lane & 3;
    const int NC = K / 32;

#define G_LOAD(buf, k0_) do {                                                   \
        int k0 = (k0_);                                                         \
        const float* Asrc; int lda, kc;                                         \
        if (k0 < K1) { Asrc = A1; lda = K1;     kc = k0; }                      \
        else         { Asrc = A2; lda = K - K1; kc = k0 - K1; }                 \
        _Pragma("unroll")                                                       \
        for (int i = 0; i < 8; i++) {                                           \
            int id = tid + i * 128;                                             \
            int row = id >> 3, c4 = (id & 7) * 4;                               \
            cp_async16(Abuf[buf] + row*GPAD + c4,                               \
                       Asrc + (size_t)(m0 + row)*lda + kc + c4);                \
        }                                                                       \
        _Pragma("unroll")                                                       \
        for (int i = 0; i < 4; i++) {                                           \
            int id = tid + i * 128;                                             \
            int row = id >> 3, c4 = (id & 7) * 4;                               \
            cp_async16(Bbuf[buf] + row*GPAD + c4,                               \
                       Bm + (size_t)(n0 + row)*K + k0 + c4);                    \
        }                                                                       \
    } while (0)

    G_LOAD(0, 0); CP_COMMIT();
    G_LOAD(1, 32); CP_COMMIT();

    float acc[4][4][4];
#pragma unroll
    for (int a = 0; a < 4; a++)
#pragma unroll
        for (int b = 0; b < 4; b++)
#pragma unroll
            for (int c = 0; c < 4; c++) acc[a][b][c] = 0.f;

    for (int c = 0; c < NC; c++) {
        if (c < NC - 1) CP_WAIT1(); else CP_WAIT0();
        __syncthreads();
        const int buf = c & 1;
        const float* Ab = Abuf[buf] + wm * 64 * GPAD;
        const float* Bb = Bbuf[buf] + wn * 32 * GPAD;
#pragma unroll
        for (int ks = 0; ks < 4; ks++) {
            const int kb = ks * 8 + lc;
            uint32_t bh[4][2], bl[4][2];
#pragma unroll
            for (int nt = 0; nt < 4; nt++) {
                splitf(Bb[(nt*8 + lr)*GPAD + kb],     bh[nt][0], bl[nt][0]);
                splitf(Bb[(nt*8 + lr)*GPAD + kb + 4], bh[nt][1], bl[nt][1]);
            }
#pragma unroll
            for (int mt = 0; mt < 4; mt++) {
                uint32_t ah[4], al[4];
                splitf(Ab[(mt*16 + lr    )*GPAD + kb],     ah[0], al[0]);
                splitf(Ab[(mt*16 + lr + 8)*GPAD + kb],     ah[1], al[1]);
                splitf(Ab[(mt*16 + lr    )*GPAD + kb + 4], ah[2], al[2]);
                splitf(Ab[(mt*16 + lr + 8)*GPAD + kb + 4], ah[3], al[3]);
#pragma unroll
                for (int nt = 0; nt < 4; nt++) {
                    mma8(acc[mt][nt], ah, bh[nt]);
                    mma8(acc[mt][nt], ah, bl[nt]);
                    mma8(acc[mt][nt], al, bh[nt]);
                }
            }
        }
        __syncthreads();
        if (c + 2 < NC) { G_LOAD(buf, (c + 2) * 32); CP_COMMIT(); }
    }

#pragma unroll
    for (int mt = 0; mt < 4; mt++) {
#pragma unroll
        for (int nt = 0; nt < 4; nt++) {
            int row = m0 + wm*64 + mt*16 + lr;
            int col = n0 + wn*32 + nt*8 + 2*lc;
            float bx = 0.f, by = 0.f;
            if (bias) { bx = bias[col]; by = bias[col + 1]; }
            *(float2*)(C + (size_t)row * Dm + col) =
                make_float2(acc[mt][nt][0] + bx, acc[mt][nt][1] + by);
            *(float2*)(C + (size_t)(row + 8) * Dm + col) =
                make_float2(acc[mt][nt][2] + bx, acc[mt][nt][3] + by);
        }
    }
#undef G_LOAD
}

// fused QKV: blockIdx.z selects {q,k,v}
__global__ __launch_bounds__(128, 3) void qkv_mma(
    const float* __restrict__ qd, const float* __restrict__ kd, const float* __restrict__ vd,
    const float* __restrict__ wt)
{
    extern __shared__ float sm[];
    const int z = blockIdx.z;
    const float* A = (z == 0) ? qd : (z == 1) ? kd : vd;
    float* C = (z == 0) ? g_qs : (z == 1) ? g_ks : g_vs;
    gemm_core(A, A, Dm, Dm, wt + (size_t)z * Dm * Dm, nullptr, C,
              blockIdx.y * 128, blockIdx.x * 64, sm);
}

__global__ __launch_bounds__(128, 3) void gemm_mma(
    const float* __restrict__ A1, const float* __restrict__ A2, int K1, int K,
    const float* __restrict__ Bm, const float* __restrict__ bias, float* __restrict__ C)
{
    extern __shared__ float sm[];
    gemm_core(A1, A2, K1, K, Bm, bias, C, blockIdx.y * 128, blockIdx.x * 64, sm);
}

// ============================================================================
// QK^T + online softmax stats. CTA = (h, b, 128 q rows); streams 8 K-tiles
// of 128 rows. 256 thr, 8 warps 2(M)x4(N), warp tile 64x32.
// ============================================================================
#define APAD 68
#define S_SMEM (3*128*APAD*4 + 512*4*3)  /* 110592 */
__global__ __launch_bounds__(256) void attn_stats_mma()
{
    extern __shared__ float sm[];
    float* Qs   = sm;
    float* Kbuf[2] = { sm + 128*APAD, sm + 2*128*APAD };
    float* redm = sm + 3*128*APAD;
    float* redl = redm + 512;
    int*   redi = (int*)(redl + 512);

    const int tid = threadIdx.x;
    const int h = blockIdx.z, b = blockIdx.y, q0 = blockIdx.x * 128;
    const int wid = tid >> 5, lane = tid & 31;
    const int wm = wid & 1, wn = wid >> 1;
    const int lr = lane >> 2, lc = lane & 3;

    const float* Qg = g_qs + ((size_t)(b * Ls + q0)) * Dm + h * 64;
    const float* Kg = g_ks + ((size_t)(b * Ls)) * Dm + h * 64;

#pragma unroll
    for (int i = 0; i < 8; i++) {
        int id = tid + i * 256;
        int row = id >> 4, c4 = (id & 15) * 4;
        cp_async16(Qs + row*APAD + c4, Qg + (size_t)row * Dm + c4);
    }
    CP_COMMIT();

#define K_LOAD(buf, t_) do {                                                    \
        _Pragma("unroll")                                                       \
        for (int i = 0; i < 8; i++) {                                           \
            int id = tid + i * 256;                                             \
            int row = id >> 4, c4 = (id & 15) * 4;                              \
            cp_async16(Kbuf[buf] + row*APAD + c4,                               \
                       Kg + (size_t)((t_)*128 + row) * Dm + c4);                \
        }                                                                       \
    } while (0)

    K_LOAD(0, 0); CP_COMMIT();
    K_LOAD(1, 1); CP_COMMIT();

    float rm[8], rl[8];
    int ridx[8];
#pragma unroll
    for (int i = 0; i < 8; i++) { rm[i] = -1e30f; rl[i] = 0.f; ridx[i] = 0; }

    for (int t = 0; t < 8; t++) {
        if (t < 7) CP_WAIT1(); else CP_WAIT0();
        __syncthreads();
        const int buf = t & 1;
        const float* Ab = Qs + wm * 64 * APAD;
        const float* Bb = Kbuf[buf] + wn * 32 * APAD;

        float acc[4][4][4];
#pragma unroll
        for (int a = 0; a < 4; a++)
#pragma unroll
            for (int bb = 0; bb < 4; bb++)
#pragma unroll
                for (int cc = 0; cc < 4; cc++) acc[a][bb][cc] = 0.f;

#pragma unroll
        for (int ks = 0; ks < 8; ks++) {
            const int kb = ks * 8 + lc;
            uint32_t bh[4][2], bl[4][2];
#pragma unroll
            for (int nt = 0; nt < 4; nt++) {
                splitf(Bb[(nt*8 + lr)*APAD + kb],     bh[nt][0], bl[nt][0]);
                splitf(Bb[(nt*8 + lr)*APAD + kb + 4], bh[nt][1], bl[nt][1]);
            }
#pragma unroll
            for (int mt = 0; mt < 4; mt++) {
                uint32_t ah[4], al[4];
                splitf(Ab[(mt*16 + lr    )*APAD + kb],     ah[0], al[0]);
                splitf(Ab[(mt*16 + lr + 8)*APAD + kb],     ah[1], al[1]);
                splitf(Ab[(mt*16 + lr    )*APAD + kb + 4], ah[2], al[2]);
                splitf(Ab[(mt*16 + lr + 8)*APAD + kb + 4], ah[3], al[3]);
#pragma unroll
                for (int nt = 0; nt < 4; nt++) {
                    mma8(acc[mt][nt], ah, bh[nt]);
                    mma8(acc[mt][nt], ah, bl[nt]);
                    mma8(acc[mt][nt], al, bh[nt]);
                }
            }
        }

        // fold tile into per-thread online stats
        const int s0 = t * 128;
#pragma unroll
        for (int mt = 0; mt < 4; mt++) {
#pragma unroll
            for (int half = 0; half < 2; half++) {
                const int r8 = mt * 2 + half;
                float lm = -1e30f; int li = 0;
#pragma unroll
                for (int nt = 0; nt < 4; nt++) {
#pragma unroll
                    for (int j = 0; j < 2; j++) {
                        float v = acc[mt][nt][half*2 + j];
                        int cl = wn*32 + nt*8 + 2*lc + j;
                        if (v > lm) { lm = v; li = cl; }
                    }
                }
                float nm = fmaxf(rm[r8], lm);
                float add = 0.f;
#pragma unroll
                for (int nt = 0; nt < 4; nt++) {
#pragma unroll
                    for (int j = 0; j < 2; j++)
                        add += fexp((acc[mt][nt][half*2 + j] - nm) * INVT);
                }
                rl[r8] = rl[r8] * fexp((rm[r8] - nm) * INVT) + add;
                if (lm > rm[r8]) ridx[r8] = s0 + li;
                rm[r8] = nm;
            }
        }
        __syncthreads();
        if (t + 2 < 8) { K_LOAD(buf, t + 2); CP_COMMIT(); }
    }

    // quad reduce (same rows, different cols)
#pragma unroll
    for (int r8 = 0; r8 < 8; r8++) {
        float m = rm[r8], l = rl[r8];
        int id = ridx[r8];
#pragma unroll
        for (int off = 1; off <= 2; off <<= 1) {
            float om = __shfl_xor_sync(0xffffffffu, m, off);
            float ol = __shfl_xor_sync(0xffffffffu, l, off);
            int   oi = __shfl_xor_sync(0xffffffffu, id, off);
            if (om > m) { l = ol + l * fexp((m - om) * INVT); m = om; id = oi; }
            else        { l = l + ol * fexp((om - m) * INVT); }
        }
        if (lc == 0) {
            int rowl = wm*64 + (r8 >> 1)*16 + (r8 & 1)*8 + lr;
            redm[rowl*4 + wn] = m;
            redl[rowl*4 + wn] = l;
            redi[rowl*4 + wn] = id;
        }
    }
    __syncthreads();

    if (tid < 128) {
        float m = redm[tid*4], l = redl[tid*4];
        int id = redi[tid*4];
#pragma unroll
        for (int w = 1; w < 4; w++) {
            float om = redm[tid*4 + w], ol = redl[tid*4 + w];
            int   oi = redi[tid*4 + w];
            if (om > m) { l = ol + l * fexp((m - om) * INVT); m = om; id = oi; }
            else        { l = l + ol * fexp((om - m) * INVT); }
        }
        int row = (h * Bn + b) * Ls + q0 + tid;
        g_p[row] = 1.0f / l;
        g_amax[row] = id;
    }
#undef K_LOAD
}

// ============================================================================
// small kernels
// ============================================================================
__global__ void wt_prep(const float* __restrict__ wq, const float* __restrict__ wk,
                        const float* __restrict__ wv)
{
    int idx = blockIdx.x * 256 + threadIdx.x;
    if (idx >= 3 * 8 * 512 * 16) return;
    int e4 = idx & 15;
    int d  = (idx >> 4) & 511;
    int h  = (idx >> 13) & 7;
    int w  = idx >> 16;
    const float* W = ((w == 0) ? wq : (w == 1) ? wk : wv) + (size_t)h * Dm * 64;
    float4 v = *(const float4*)(W + d * 64 + e4 * 4);
    float* WT = g_wt + (size_t)w * Dm * Dm;
    int n = h * 64 + e4 * 4;
    WT[(size_t)(n + 0) * Dm + d] = v.x;
    WT[(size_t)(n + 1) * Dm + d] = v.y;
    WT[(size_t)(n + 2) * Dm + d] = v.z;
    WT[(size_t)(n + 3) * Dm + d] = v.w;
}

__global__ void scatter_kernel(float* __restrict__ attn)
{
    int r = blockIdx.x * blockDim.x + threadIdx.x;
    if (r >= NROWS) return;
    attn[(size_t)r * Ls + g_amax[r]] = g_p[r];
}

__global__ void gather_kernel()
{
    int idx = blockIdx.x * blockDim.x + threadIdx.x;
    if (idx >= M_ALL * Dm) return;
    int e = idx & 63;
    int h = (idx >> 6) & 7;
    int m = idx >> 9;               // b*L + q
    int b = m >> 10;
    int q = m & 1023;
    int row = (h * Bn + b) * Ls + q;
    float p = g_p[row];
    int   s = g_amax[row];
    g_headout[idx] = p * g_vs[((size_t)(b * Ls + s)) * Dm + h * 64 + e];
}

// ============================================================================
extern "C" void kernel_launch(void* const* d_in, const int* in_sizes, int n_in,
                              void* d_out, int out_size)
{
    const float* q_data = (const float*)d_in[0];
    const float* k_data = (const float*)d_in[1];
    const float* v_data = (const float*)d_in[2];
    const float* w_qs   = (const float*)d_in[3];
    const float* w_ks   = (const float*)d_in[4];
    const float* w_vs   = (const float*)d_in[5];
    const float* proj_w = (const float*)d_in[6];
    const float* proj_b = (const float*)d_in[7];
    const float* lin_w  = (const float*)d_in[8];
    const float* lin_b  = (const float*)d_in[9];

    float* out  = (float*)d_out;                    // [B, L, D]
    float* attn = out + OUT_ELEMS;                  // [H*B, L, L]

    float *p_ho, *p_po, *p_wt;
    cudaGetSymbolAddress((void**)&p_ho, g_headout);
    cudaGetSymbolAddress((void**)&p_po, g_projout);
    cudaGetSymbolAddress((void**)&p_wt, g_wt);

    cudaFuncSetAttribute(qkv_mma,  cudaFuncAttributeMaxDynamicSharedMemorySize, G_SMEM);
    cudaFuncSetAttribute(gemm_mma, cudaFuncAttributeMaxDynamicSharedMemorySize, G_SMEM);
    cudaFuncSetAttribute(attn_stats_mma, cudaFuncAttributeMaxDynamicSharedMemorySize, S_SMEM);

    // 0) transpose qkv weights into [n][k] form
    wt_prep<<<768, 256>>>(w_qs, w_ks, w_vs);

    // 1) fused QKV projections (tensor cores, tf32 3-product)
    qkv_mma<<<dim3(8, 128, 3), 128, G_SMEM>>>(q_data, k_data, v_data, p_wt);

    // 2) QK^T + softmax stats (fused, no dense scores)
    attn_stats_mma<<<dim3(8, 16, 8), 256, S_SMEM>>>();

    // 3) dense attn output: zeros + single nonzero per row
    cudaMemsetAsync(attn, 0, (size_t)NROWS * Ls * sizeof(float));
    scatter_kernel<<<(NROWS + 255) / 256, 256>>>(attn);

    // 4) attn @ V collapsed to gather
    gather_kernel<<<(M_ALL * Dm + 255) / 256, 256>>>();

    // 5) output projection
    gemm_mma<<<dim3(8, 128), 128, G_SMEM>>>(p_ho, p_ho, Dm, Dm, proj_w, proj_b, p_po);

    // 6) final linear: out = [q_data | projout] @ lin_w^T + lin_b
    gemm_mma<<<dim3(8, 128), 128, G_SMEM>>>(q_data, p_po, Dm, 2*Dm, lin_w, lin_b, out);
}

// round 5
// speedup vs baseline: 1.7725x; 1.1769x over previous
#include <cuda_runtime.h>
#include <cstdint>

#define Hh 8
#define Bn 16
#define Ls 1024
#define Dm 512
#define M_ALL (Bn*Ls)              /* 16384 */
#define OUT_ELEMS (Bn*Ls*Dm)       /* 8388608 */
#define NROWS (Hh*Bn*Ls)           /* 131072 */
#define INVT 0.044194173824159216f /* 1/sqrt(512) */

// ---------------- static device scratch ----------------
__device__ float g_qs[M_ALL*Dm];        // [m][h*64+e]
__device__ float g_ks[M_ALL*Dm];
__device__ float g_vs[M_ALL*Dm];
__device__ float g_headout[M_ALL*Dm];   // [m][h*64+e]
__device__ float g_projout[M_ALL*Dm];
__device__ float g_wt[3*Dm*Dm];         // transposed qkv weights: [w][n=h*64+e][k=d]
__device__ float g_p[NROWS];
__device__ int   g_amax[NROWS];

// ---------------- helpers ----------------
__device__ __forceinline__ uint32_t smem_u32(const void* p) {
    uint32_t a;
    asm("{ .reg .u64 t; cvta.to.shared.u64 t, %1; cvt.u32.u64 %0, t; }" : "=r"(a) : "l"(p));
    return a;
}
__device__ __forceinline__ void cp_async16(void* sdst, const void* gsrc) {
    uint32_t s = smem_u32(sdst);
    asm volatile("cp.async.ca.shared.global [%0], [%1], 16;" :: "r"(s), "l"(gsrc));
}
#define CP_COMMIT() asm volatile("cp.async.commit_group;" ::: "memory")
#define CP_WAIT1()  asm volatile("cp.async.wait_group 1;" ::: "memory")
#define CP_WAIT0()  asm volatile("cp.async.wait_group 0;" ::: "memory")

// fp32 -> tf32 hi (rounded) + raw fp32 residual (exact; HMMA truncates)
__device__ __forceinline__ void splitf(float x, uint32_t& hi, uint32_t& lo) {
    uint32_t h;
    asm("cvt.rna.tf32.f32 %0, %1;" : "=r"(h) : "f"(x));
    hi = h;
    lo = __float_as_uint(x - __uint_as_float(h));
}
__device__ __forceinline__ void mma8(float* d, const uint32_t* a, const uint32_t* b) {
    asm volatile("mma.sync.aligned.m16n8k8.row.col.f32.tf32.tf32.f32 "
                 "{%0,%1,%2,%3}, {%4,%5,%6,%7}, {%8,%9}, {%0,%1,%2,%3};"
                 : "+f"(d[0]), "+f"(d[1]), "+f"(d[2]), "+f"(d[3])
                 : "r"(a[0]), "r"(a[1]), "r"(a[2]), "r"(a[3]),
                   "r"(b[0]), "r"(b[1]));
}
// bf16 pair split: two consecutive-k fp32 -> packed bf16x2 hi + bf16x2 lo
__device__ __forceinline__ void split2(float x0, float x1, uint32_t& hi, uint32_t& lo) {
    uint32_t h;
    asm("cvt.rn.bf16x2.f32 %0, %1, %2;" : "=r"(h) : "f"(x1), "f"(x0));
    float h0 = __uint_as_float(h << 16);
    float h1 = __uint_as_float(h & 0xffff0000u);
    float r0 = x0 - h0, r1 = x1 - h1;
    asm("cvt.rn.bf16x2.f32 %0, %1, %2;" : "=r"(lo) : "f"(r1), "f"(r0));
    hi = h;
}
__device__ __forceinline__ void mma16(float* d, const uint32_t* a, const uint32_t* b) {
    asm volatile("mma.sync.aligned.m16n8k16.row.col.f32.bf16.bf16.f32 "
                 "{%0,%1,%2,%3}, {%4,%5,%6,%7}, {%8,%9}, {%0,%1,%2,%3};"
                 : "+f"(d[0]), "+f"(d[1]), "+f"(d[2]), "+f"(d[3])
                 : "r"(a[0]), "r"(a[1]), "r"(a[2]), "r"(a[3]),
                   "r"(b[0]), "r"(b[1]));
}
// fast exp via exp2 polynomial (FMA pipe only, ~2e-6 rel err)
__device__ __forceinline__ float fexp(float t) {
    float z = t * 1.4426950408889634f;
    z = fmaxf(z, -120.f);
    int   e  = __float2int_rn(z);
    float f  = z - (float)e;                 // [-0.5, 0.5]
    float p = 1.3333558146428443e-3f;
    p = fmaf(p, f, 9.6181291976233960e-3f);
    p = fmaf(p, f, 5.5504108664821580e-2f);
    p = fmaf(p, f, 2.4022650695910071e-1f);
    p = fmaf(p, f, 6.9314718055994531e-1f);
    p = fmaf(p, f, 1.0f);
    return __int_as_float(__float_as_int(p) + (e << 23));
}

// ============================================================================
// shared GEMM scaffolding: 128x64 CTA tile, 128 thr = 4 warps 2(M)x2(N),
// warp tile 64x32, K chunks of 32, cp.async double buffer, 3 CTAs/SM.
// smem: A[2][128][36] + B[2][64][36] fp32 = 55296 B
// ============================================================================
#define GPAD 36
#define G_SMEM ((2*128*GPAD + 2*64*GPAD)*4)   /* 55296 */

#define G_LOAD(buf, k0_) do {                                                   \
        int k0 = (k0_);                                                         \
        const float* Asrc; int lda, kc;                                         \
        if (k0 < K1) { Asrc = A1; lda = K1;     kc = k0; }                      \
        else         { Asrc = A2; lda = K - K1; kc = k0 - K1; }                 \
        _Pragma("unroll")                                                       \
        for (int i = 0; i < 8; i++) {                                           \
            int id = tid + i * 128;                                             \
            int row = id >> 3, c4 = (id & 7) * 4;                               \
            cp_async16(Abuf[buf] + row*GPAD + c4,                               \
                       Asrc + (size_t)(m0 + row)*lda + kc + c4);                \
        }                                                                       \
        _Pragma("unroll")                                                       \
        for (int i = 0; i < 4; i++) {                                           \
            int id = tid + i * 128;                                             \
            int row = id >> 3, c4 = (id & 7) * 4;                               \
            cp_async16(Bbuf[buf] + row*GPAD + c4,                               \
                       Bm + (size_t)(n0 + row)*K + k0 + c4);                    \
        }                                                                       \
    } while (0)

#define G_EPILOGUE()                                                             \
    _Pragma("unroll")                                                            \
    for (int mt = 0; mt < 4; mt++) {                                             \
        _Pragma("unroll")                                                        \
        for (int nt = 0; nt < 4; nt++) {                                         \
            int row = m0 + wm*64 + mt*16 + lr;                                   \
            int col = n0 + wn*32 + nt*8 + 2*lc;                                  \
            float bx = 0.f, by = 0.f;                                            \
            if (bias) { bx = bias[col]; by = bias[col + 1]; }                    \
            *(float2*)(C + (size_t)row * Dm + col) =                             \
                make_float2(acc[mt][nt][0] + bx, acc[mt][nt][1] + by);           \
            *(float2*)(C + (size_t)(row + 8) * Dm + col) =                       \
                make_float2(acc[mt][nt][2] + bx, acc[mt][nt][3] + by);           \
        }                                                                        \
    }

// ---- tf32 3-product core (argmax-critical paths: Q/K projections) ----
__device__ __forceinline__ void gemm_core_tf32(
    const float* __restrict__ A1, const float* __restrict__ A2, int K1, int K,
    const float* __restrict__ Bm, const float* __restrict__ bias,
    float* __restrict__ C, int m0, int n0, float* sm)
{
    float* Abuf[2] = { sm,              sm + 128*GPAD };
    float* Bbuf[2] = { sm + 2*128*GPAD, sm + 2*128*GPAD + 64*GPAD };
    const int tid = threadIdx.x;
    const int wid = tid >> 5, lane = tid & 31;
    const int wm = wid & 1, wn = wid >> 1;
    const int lr = lane >> 2, lc = lane & 3;
    const int NC = K / 32;

    G_LOAD(0, 0); CP_COMMIT();
    G_LOAD(1, 32); CP_COMMIT();

    float acc[4][4][4];
#pragma unroll
    for (int a = 0; a < 4; a++)
#pragma unroll
        for (int b = 0; b < 4; b++)
#pragma unroll
            for (int c = 0; c < 4; c++) acc[a][b][c] = 0.f;

    for (int c = 0; c < NC; c++) {
        if (c < NC - 1) CP_WAIT1(); else CP_WAIT0();
        __syncthreads();
        const int buf = c & 1;
        const float* Ab = Abuf[buf] + wm * 64 * GPAD;
        const float* Bb = Bbuf[buf] + wn * 32 * GPAD;
#pragma unroll
        for (int ks = 0; ks < 4; ks++) {
            const int kb = ks * 8 + lc;
            uint32_t bh[4][2], bl[4][2];
#pragma unroll
            for (int nt = 0; nt < 4; nt++) {
                splitf(Bb[(nt*8 + lr)*GPAD + kb],     bh[nt][0], bl[nt][0]);
                splitf(Bb[(nt*8 + lr)*GPAD + kb + 4], bh[nt][1], bl[nt][1]);
            }
#pragma unroll
            for (int mt = 0; mt < 4; mt++) {
                uint32_t ah[4], al[4];
                splitf(Ab[(mt*16 + lr    )*GPAD + kb],     ah[0], al[0]);
                splitf(Ab[(mt*16 + lr + 8)*GPAD + kb],     ah[1], al[1]);
                splitf(Ab[(mt*16 + lr    )*GPAD + kb + 4], ah[2], al[2]);
                splitf(Ab[(mt*16 + lr + 8)*GPAD + kb + 4], ah[3], al[3]);
#pragma unroll
                for (int nt = 0; nt < 4; nt++) {
                    mma8(acc[mt][nt], ah, bh[nt]);
                    mma8(acc[mt][nt], ah, bl[nt]);
                    mma8(acc[mt][nt], al, bh[nt]);
                }
            }
        }
        __syncthreads();
        if (c + 2 < NC) { G_LOAD(buf, (c + 2) * 32); CP_COMMIT(); }
    }
    G_EPILOGUE()
}

// ---- bf16 split 3-product core (magnitude-only paths: V/proj/lin), 2x rate ----
__device__ __forceinline__ void gemm_core_bf(
    const float* __restrict__ A1, const float* __restrict__ A2, int K1, int K,
    const float* __restrict__ Bm, const float* __restrict__ bias,
    float* __restrict__ C, int m0, int n0, float* sm)
{
    float* Abuf[2] = { sm,              sm + 128*GPAD };
    float* Bbuf[2] = { sm + 2*128*GPAD, sm + 2*128*GPAD + 64*GPAD };
    const int tid = threadIdx.x;
    const int wid = tid >> 5, lane = tid & 31;
    const int wm = wid & 1, wn = wid >> 1;
    const int lr = lane >> 2, lc = lane & 3;
    const int NC = K / 32;

    G_LOAD(0, 0); CP_COMMIT();
    G_LOAD(1, 32); CP_COMMIT();

    float acc[4][4][4];
#pragma unroll
    for (int a = 0; a < 4; a++)
#pragma unroll
        for (int b = 0; b < 4; b++)
#pragma unroll
            for (int c = 0; c < 4; c++) acc[a][b][c] = 0.f;

    for (int c = 0; c < NC; c++) {
        if (c < NC - 1) CP_WAIT1(); else CP_WAIT0();
        __syncthreads();
        const int buf = c & 1;
        const float* Ab = Abuf[buf] + wm * 64 * GPAD;
        const float* Bb = Bbuf[buf] + wn * 32 * GPAD;
#pragma unroll
        for (int ks = 0; ks < 2; ks++) {            // k16 steps
            const int kb = ks * 16 + 2 * lc;
            uint32_t bh[4][2], bl[4][2];
#pragma unroll
            for (int nt = 0; nt < 4; nt++) {
                float2 b0 = *(const float2*)(Bb + (nt*8 + lr)*GPAD + kb);
                float2 b1 = *(const float2*)(Bb + (nt*8 + lr)*GPAD + kb + 8);
                split2(b0.x, b0.y, bh[nt][0], bl[nt][0]);
                split2(b1.x, b1.y, bh[nt][1], bl[nt][1]);
            }
#pragma unroll
            for (int mt = 0; mt < 4; mt++) {
                uint32_t ah[4], al[4];
                float2 a00 = *(const float2*)(Ab + (mt*16 + lr    )*GPAD + kb);
                float2 a10 = *(const float2*)(Ab + (mt*16 + lr + 8)*GPAD + kb);
                float2 a01 = *(const float2*)(Ab + (mt*16 + lr    )*GPAD + kb + 8);
                float2 a11 = *(const float2*)(Ab + (mt*16 + lr + 8)*GPAD + kb + 8);
                split2(a00.x, a00.y, ah[0], al[0]);
                split2(a10.x, a10.y, ah[1], al[1]);
                split2(a01.x, a01.y, ah[2], al[2]);
                split2(a11.x, a11.y, ah[3], al[3]);
#pragma unroll
                for (int nt = 0; nt < 4; nt++) {
                    mma16(acc[mt][nt], ah, bh[nt]);
                    mma16(acc[mt][nt], ah, bl[nt]);
                    mma16(acc[mt][nt], al, bh[nt]);
                }
            }
        }
        __syncthreads();
        if (c + 2 < NC) { G_LOAD(buf, (c + 2) * 32); CP_COMMIT(); }
    }
    G_EPILOGUE()
}

// Q/K projections (tf32): blockIdx.z selects {q,k}
__global__ __launch_bounds__(128, 3) void qk_mma(
    const float* __restrict__ qd, const float* __restrict__ kd,
    const float* __restrict__ wt)
{
    extern __shared__ float sm[];
    const int z = blockIdx.z;
    const float* A = (z == 0) ? qd : kd;
    float* C = (z == 0) ? g_qs : g_ks;
    gemm_core_tf32(A, A, Dm, Dm, wt + (size_t)z * Dm * Dm, nullptr, C,
                   blockIdx.y * 128, blockIdx.x * 64, sm);
}

__global__ __launch_bounds__(128, 3) void gemm_bf_mma(
    const float* __restrict__ A1, const float* __restrict__ A2, int K1, int K,
    const float* __restrict__ Bm, const float* __restrict__ bias, float* __restrict__ C)
{
    extern __shared__ float sm[];
    gemm_core_bf(A1, A2, K1, K, Bm, bias, C, blockIdx.y * 128, blockIdx.x * 64, sm);
}

// ============================================================================
// QK^T + online softmax stats (tf32 3-product). CTA = (h, b, 128 q rows),
// 128 thr = 4 warps 2(M)x2(N), warp tile 64x32; streams 16 K-tiles of 64 rows.
// smem 72.7KB -> 3 CTAs/SM.
// ============================================================================
#define APAD 68
#define S_SMEM ((128*APAD + 2*64*APAD)*4 + 256*4*3)  /* 69632+3072=72704 */
__global__ __launch_bounds__(128, 3) void attn_stats_mma()
{
    extern __shared__ float sm[];
    float* Qs   = sm;
    float* Kbuf[2] = { sm + 128*APAD, sm + 128*APAD + 64*APAD };
    float* redm = sm + 128*APAD + 2*64*APAD;
    float* redl = redm + 256;
    int*   redi = (int*)(redl + 256);

    const int tid = threadIdx.x;
    const int h = blockIdx.z, b = blockIdx.y, q0 = blockIdx.x * 128;
    const int wid = tid >> 5, lane = tid & 31;
    const int wm = wid & 1, wn = wid >> 1;              // wn in {0,1}
    const int lr = lane >> 2, lc = lane & 3;

    const float* Qg = g_qs + ((size_t)(b * Ls + q0)) * Dm + h * 64;
    const float* Kg = g_ks + ((size_t)(b * Ls)) * Dm + h * 64;

    // Q tile: 128 rows x 64 floats
#pragma unroll
    for (int i = 0; i < 16; i++) {
        int id = tid + i * 128;
        int row = id >> 4, c4 = (id & 15) * 4;
        cp_async16(Qs + row*APAD + c4, Qg + (size_t)row * Dm + c4);
    }
    CP_COMMIT();

#define K_LOAD(buf, t_) do {                                                    \
        _Pragma("unroll")                                                       \
        for (int i = 0; i < 8; i++) {                                           \
            int id = tid + i * 128;                                             \
            int row = id >> 4, c4 = (id & 15) * 4;                              \
            cp_async16(Kbuf[buf] + row*APAD + c4,                               \
                       Kg + (size_t)((t_)*64 + row) * Dm + c4);                 \
        }                                                                       \
    } while (0)

    K_LOAD(0, 0); CP_COMMIT();
    K_LOAD(1, 1); CP_COMMIT();

    float rm[8], rl[8];
    int ridx[8];
#pragma unroll
    for (int i = 0; i < 8; i++) { rm[i] = -1e30f; rl[i] = 0.f; ridx[i] = 0; }

    for (int t = 0; t < 16; t++) {
        if (t < 15) CP_WAIT1(); else CP_WAIT0();
        __syncthreads();
        const int buf = t & 1;
        const float* Ab = Qs + wm * 64 * APAD;
        const float* Bb = Kbuf[buf] + wn * 32 * APAD;

        float acc[4][4][4];
#pragma unroll
        for (int a = 0; a < 4; a++)
#pragma unroll
            for (int bb = 0; bb < 4; bb++)
#pragma unroll
                for (int cc = 0; cc < 4; cc++) acc[a][bb][cc] = 0.f;

#pragma unroll
        for (int ks = 0; ks < 8; ks++) {
            const int kb = ks * 8 + lc;
            uint32_t bh[4][2], bl[4][2];
#pragma unroll
            for (int nt = 0; nt < 4; nt++) {
                splitf(Bb[(nt*8 + lr)*APAD + kb],     bh[nt][0], bl[nt][0]);
                splitf(Bb[(nt*8 + lr)*APAD + kb + 4], bh[nt][1], bl[nt][1]);
            }
#pragma unroll
            for (int mt = 0; mt < 4; mt++) {
                uint32_t ah[4], al[4];
                splitf(Ab[(mt*16 + lr    )*APAD + kb],     ah[0], al[0]);
                splitf(Ab[(mt*16 + lr + 8)*APAD + kb],     ah[1], al[1]);
                splitf(Ab[(mt*16 + lr    )*APAD + kb + 4], ah[2], al[2]);
                splitf(Ab[(mt*16 + lr + 8)*APAD + kb + 4], ah[3], al[3]);
#pragma unroll
                for (int nt = 0; nt < 4; nt++) {
                    mma8(acc[mt][nt], ah, bh[nt]);
                    mma8(acc[mt][nt], ah, bl[nt]);
                    mma8(acc[mt][nt], al, bh[nt]);
                }
            }
        }

        // fold tile into per-thread online stats
        const int s0 = t * 64;
#pragma unroll
        for (int mt = 0; mt < 4; mt++) {
#pragma unroll
            for (int half = 0; half < 2; half++) {
                const int r8 = mt * 2 + half;
                float lm = -1e30f; int li = 0;
#pragma unroll
                for (int nt = 0; nt < 4; nt++) {
#pragma unroll
                    for (int j = 0; j < 2; j++) {
                        float v = acc[mt][nt][half*2 + j];
                        int cl = wn*32 + nt*8 + 2*lc + j;
                        if (v > lm) { lm = v; li = cl; }
                    }
                }
                float nm = fmaxf(rm[r8], lm);
                float add = 0.f;
#pragma unroll
                for (int nt = 0; nt < 4; nt++) {
#pragma unroll
                    for (int j = 0; j < 2; j++)
                        add += fexp((acc[mt][nt][half*2 + j] - nm) * INVT);
                }
                rl[r8] = rl[r8] * fexp((rm[r8] - nm) * INVT) + add;
                if (lm > rm[r8]) ridx[r8] = s0 + li;
                rm[r8] = nm;
            }
        }
        __syncthreads();
        if (t + 2 < 16) { K_LOAD(buf, t + 2); CP_COMMIT(); }
    }

    // quad reduce over lc (same rows, different cols)
#pragma unroll
    for (int r8 = 0; r8 < 8; r8++) {
        float m = rm[r8], l = rl[r8];
        int id = ridx[r8];
#pragma unroll
        for (int off = 1; off <= 2; off <<= 1) {
            float om = __shfl_xor_sync(0xffffffffu, m, off);
            float ol = __shfl_xor_sync(0xffffffffu, l, off);
            int   oi = __shfl_xor_sync(0xffffffffu, id, off);
            if (om > m) { l = ol + l * fexp((m - om) * INVT); m = om; id = oi; }
            else        { l = l + ol * fexp((om - m) * INVT); }
        }
        if (lc == 0) {
            int rowl = wm*64 + (r8 >> 1)*16 + (r8 & 1)*8 + lr;
            redm[rowl*2 + wn] = m;
            redl[rowl*2 + wn] = l;
            redi[rowl*2 + wn] = id;
        }
    }
    __syncthreads();

    {
        float m = redm[tid*2], l = redl[tid*2];
        int id = redi[tid*2];
        float om = redm[tid*2 + 1], ol = redl[tid*2 + 1];
        int   oi = redi[tid*2 + 1];
        if (om > m) { l = ol + l * fexp((m - om) * INVT); m = om; id = oi; }
        else        { l = l + ol * fexp((om - m) * INVT); }
        int row = (h * Bn + b) * Ls + q0 + tid;
        g_p[row] = 1.0f / l;
        g_amax[row] = id;
    }
#undef K_LOAD
}

// ============================================================================
// small kernels
// ============================================================================
__global__ void wt_prep(const float* __restrict__ wq, const float* __restrict__ wk,
                        const float* __restrict__ wv)
{
    int idx = blockIdx.x * 256 + threadIdx.x;
    if (idx >= 3 * 8 * 512 * 16) return;
    int e4 = idx & 15;
    int d  = (idx >> 4) & 511;
    int h  = (idx >> 13) & 7;
    int w  = idx >> 16;
    const float* W = ((w == 0) ? wq : (w == 1) ? wk : wv) + (size_t)h * Dm * 64;
    float4 v = *(const float4*)(W + d * 64 + e4 * 4);
    float* WT = g_wt + (size_t)w * Dm * Dm;
    int n = h * 64 + e4 * 4;
    WT[(size_t)(n + 0) * Dm + d] = v.x;
    WT[(size_t)(n + 1) * Dm + d] = v.y;
    WT[(size_t)(n + 2) * Dm + d] = v.z;
    WT[(size_t)(n + 3) * Dm + d] = v.w;
}

__global__ void scatter_kernel(float* __restrict__ attn)
{
    int r = blockIdx.x * blockDim.x + threadIdx.x;
    if (r >= NROWS) return;
    attn[(size_t)r * Ls + g_amax[r]] = g_p[r];
}

__global__ void gather_kernel()
{
    int idx = blockIdx.x * blockDim.x + threadIdx.x;
    if (idx >= M_ALL * Dm) return;
    int e = idx & 63;
    int h = (idx >> 6) & 7;
    int m = idx >> 9;               // b*L + q
    int b = m >> 10;
    int q = m & 1023;
    int row = (h * Bn + b) * Ls + q;
    float p = g_p[row];
    int   s = g_amax[row];
    g_headout[idx] = p * g_vs[((size_t)(b * Ls + s)) * Dm + h * 64 + e];
}

// ============================================================================
extern "C" void kernel_launch(void* const* d_in, const int* in_sizes, int n_in,
                              void* d_out, int out_size)
{
    const float* q_data = (const float*)d_in[0];
    const float* k_data = (const float*)d_in[1];
    const float* v_data = (const float*)d_in[2];
    const float* w_qs   = (const float*)d_in[3];
    const float* w_ks   = (const float*)d_in[4];
    const float* w_vs   = (const float*)d_in[5];
    const float* proj_w = (const float*)d_in[6];
    const float* proj_b = (const float*)d_in[7];
    const float* lin_w  = (const float*)d_in[8];
    const float* lin_b  = (const float*)d_in[9];

    float* out  = (float*)d_out;                    // [B, L, D]
    float* attn = out + OUT_ELEMS;                  // [H*B, L, L]

    float *p_vs, *p_ho, *p_po, *p_wt;
    cudaGetSymbolAddress((void**)&p_vs, g_vs);
    cudaGetSymbolAddress((void**)&p_ho, g_headout);
    cudaGetSymbolAddress((void**)&p_po, g_projout);
    cudaGetSymbolAddress((void**)&p_wt, g_wt);

    cudaFuncSetAttribute(qk_mma,      cudaFuncAttributeMaxDynamicSharedMemorySize, G_SMEM);
    cudaFuncSetAttribute(gemm_bf_mma, cudaFuncAttributeMaxDynamicSharedMemorySize, G_SMEM);
    cudaFuncSetAttribute(attn_stats_mma, cudaFuncAttributeMaxDynamicSharedMemorySize, S_SMEM);

    // 0) transpose qkv weights into [n][k] form
    wt_prep<<<768, 256>>>(w_qs, w_ks, w_vs);

    // 1) Q/K projections (tf32 3-product: argmax-critical)
    qk_mma<<<dim3(8, 128, 2), 128, G_SMEM>>>(q_data, k_data, p_wt);

    // 1b) V projection (bf16 split 3-product: magnitude-only)
    gemm_bf_mma<<<dim3(8, 128), 128, G_SMEM>>>(v_data, v_data, Dm, Dm,
                                               p_wt + 2*Dm*Dm, nullptr, p_vs);

    // 2) QK^T + softmax stats (tf32 3-product, fused, no dense scores)
    attn_stats_mma<<<dim3(8, 16, 8), 128, S_SMEM>>>();

    // 3) dense attn output: zeros + single nonzero per row
    cudaMemsetAsync(attn, 0, (size_t)NROWS * Ls * sizeof(float));
    scatter_kernel<<<(NROWS + 255) / 256, 256>>>(attn);

    // 4) attn @ V collapsed to gather
    gather_kernel<<<(M_ALL * Dm + 255) / 256, 256>>>();

    // 5) output projection (bf16)
    gemm_bf_mma<<<dim3(8, 128), 128, G_SMEM>>>(p_ho, p_ho, Dm, Dm, proj_w, proj_b, p_po);

    // 6) final linear (bf16): out = [q_data | projout] @ lin_w^T + lin_b
    gemm_bf_mma<<<dim3(8, 128), 128, G_SMEM>>>(q_data, p_po, Dm, 2*Dm, lin_w, lin_b, out);
}

// round 6
// speedup vs baseline: 1.9698x; 1.1113x over previous
#include <cuda_runtime.h>
#include <cstdint>

#define Hh 8
#define Bn 16
#define Ls 1024
#define Dm 512
#define M_ALL (Bn*Ls)              /* 16384 */
#define OUT_ELEMS (Bn*Ls*Dm)       /* 8388608 */
#define NROWS (Hh*Bn*Ls)           /* 131072 */
#define INVT 0.044194173824159216f /* 1/sqrt(512) */
#define CC   0.0637588536f         /* invT * log2(e) */

// ---------------- static device scratch ----------------
__device__ float g_qs[M_ALL*Dm];        // [m][h*64+e]
__device__ float g_ks[M_ALL*Dm];
__device__ float g_vs[M_ALL*Dm];
__device__ float g_headout[M_ALL*Dm];   // [m][h*64+e]
__device__ float g_projout[M_ALL*Dm];
__device__ float g_p[NROWS];
__device__ int   g_amax[NROWS];

// ---------------- helpers ----------------
__device__ __forceinline__ uint32_t smem_u32(const void* p) {
    uint32_t a;
    asm("{ .reg .u64 t; cvta.to.shared.u64 t, %1; cvt.u32.u64 %0, t; }" : "=r"(a) : "l"(p));
    return a;
}
__device__ __forceinline__ void cp_async16(void* sdst, const void* gsrc) {
    uint32_t s = smem_u32(sdst);
    asm volatile("cp.async.ca.shared.global [%0], [%1], 16;" :: "r"(s), "l"(gsrc));
}
#define CP_COMMIT() asm volatile("cp.async.commit_group;" ::: "memory")
#define CP_WAIT1()  asm volatile("cp.async.wait_group 1;" ::: "memory")
#define CP_WAIT0()  asm volatile("cp.async.wait_group 0;" ::: "memory")

// fp32 -> tf32 hi (rounded) + raw fp32 residual (exact; HMMA truncates)
__device__ __forceinline__ void splitf(float x, uint32_t& hi, uint32_t& lo) {
    uint32_t h;
    asm("cvt.rna.tf32.f32 %0, %1;" : "=r"(h) : "f"(x));
    hi = h;
    lo = __float_as_uint(x - __uint_as_float(h));
}
__device__ __forceinline__ void mma8(float* d, const uint32_t* a, const uint32_t* b) {
    asm volatile("mma.sync.aligned.m16n8k8.row.col.f32.tf32.tf32.f32 "
                 "{%0,%1,%2,%3}, {%4,%5,%6,%7}, {%8,%9}, {%0,%1,%2,%3};"
                 : "+f"(d[0]), "+f"(d[1]), "+f"(d[2]), "+f"(d[3])
                 : "r"(a[0]), "r"(a[1]), "r"(a[2]), "r"(a[3]),
                   "r"(b[0]), "r"(b[1]));
}
// bf16 pair split: two consecutive-k fp32 -> packed bf16x2 hi + bf16x2 lo
__device__ __forceinline__ void split2(float x0, float x1, uint32_t& hi, uint32_t& lo) {
    uint32_t h;
    asm("cvt.rn.bf16x2.f32 %0, %1, %2;" : "=r"(h) : "f"(x1), "f"(x0));
    float h0 = __uint_as_float(h << 16);
    float h1 = __uint_as_float(h & 0xffff0000u);
    float r0 = x0 - h0, r1 = x1 - h1;
    asm("cvt.rn.bf16x2.f32 %0, %1, %2;" : "=r"(lo) : "f"(r1), "f"(r0));
    hi = h;
}
__device__ __forceinline__ void mma16(float* d, const uint32_t* a, const uint32_t* b) {
    asm volatile("mma.sync.aligned.m16n8k16.row.col.f32.bf16.bf16.f32 "
                 "{%0,%1,%2,%3}, {%4,%5,%6,%7}, {%8,%9}, {%0,%1,%2,%3};"
                 : "+f"(d[0]), "+f"(d[1]), "+f"(d[2]), "+f"(d[3])
                 : "r"(a[0]), "r"(a[1]), "r"(a[2]), "r"(a[3]),
                   "r"(b[0]), "r"(b[1]));
}
// 2^z for |z| small: 5-term poly on [-0.5,0.5] + exponent add (~2e-6 rel err)
__device__ __forceinline__ float fexp2s(float z) {
    int   e  = __float2int_rn(z);
    float f  = z - (float)e;
    float p = 1.3333558146428443e-3f;
    p = fmaf(p, f, 9.6181291976233960e-3f);
    p = fmaf(p, f, 5.5504108664821580e-2f);
    p = fmaf(p, f, 2.4022650695910071e-1f);
    p = fmaf(p, f, 6.9314718055994531e-1f);
    p = fmaf(p, f, 1.0f);
    return __int_as_float(__float_as_int(p) + (e << 23));
}

// ============================================================================
// shared GEMM scaffolding: 128x64 CTA tile, 128 thr = 4 warps 2(M)x2(N),
// warp tile 64x32, K chunks of 32, cp.async double buffer, 3 CTAs/SM.
// ============================================================================
#define GPAD 36
#define BTPAD 68
#define G_SMEM ((2*128*GPAD + 2*64*GPAD)*4)       /* 55296: [n][k]-weights form */
#define G_SMEM_BT ((2*128*GPAD + 2*32*BTPAD)*4)   /* 54272: [k][n]-weights form */

// A loader (activations, [m][k] gmem, possibly concatenated)
#define A_LOAD(buf, k0_) do {                                                    \
        int k0 = (k0_);                                                          \
        const float* Asrc; int lda, kc;                                          \
        if (k0 < K1) { Asrc = A1; lda = K1;     kc = k0; }                       \
        else         { Asrc = A2; lda = K - K1; kc = k0 - K1; }                  \
        _Pragma("unroll")                                                        \
        for (int i = 0; i < 8; i++) {                                            \
            int id = tid + i * 128;                                              \
            int row = id >> 3, c4 = (id & 7) * 4;                                \
            cp_async16(Abuf[buf] + row*GPAD + c4,                                \
                       Asrc + (size_t)(m0 + row)*lda + kc + c4);                 \
        }                                                                         \
    } while (0)

#define G_EPILOGUE()                                                             \
    _Pragma("unroll")                                                            \
    for (int mt = 0; mt < 4; mt++) {                                             \
        _Pragma("unroll")                                                        \
        for (int nt = 0; nt < 4; nt++) {                                         \
            int row = m0 + wm*64 + mt*16 + lr;                                   \
            int col = n0 + wn*32 + nt*8 + 2*lc;                                  \
            float bx = 0.f, by = 0.f;                                            \
            if (bias) { bx = bias[col]; by = bias[col + 1]; }                    \
            *(float2*)(C + (size_t)row * Dm + col) =                             \
                make_float2(acc[mt][nt][0] + bx, acc[mt][nt][1] + by);           \
            *(float2*)(C + (size_t)(row + 8) * Dm + col) =                       \
                make_float2(acc[mt][nt][2] + bx, acc[mt][nt][3] + by);           \
        }                                                                        \
    }

// ---- tf32 3-product core, B streamed from W[h][d][e] as [k][n] tiles ----
// (Q/K projections: argmax-critical). n-tile (64) == one head.
__device__ __forceinline__ void gemm_core_tf32_bt(
    const float* __restrict__ A1, const float* __restrict__ Wh,
    float* __restrict__ C, int m0, int n0, float* sm)
{
    const float* A2 = A1; const int K1 = Dm, K = Dm;
    const float* bias = nullptr;
    float* Abuf[2] = { sm,              sm + 128*GPAD };
    float* Bbuf[2] = { sm + 2*128*GPAD, sm + 2*128*GPAD + 32*BTPAD };
    const int tid = threadIdx.x;
    const int wid = tid >> 5, lane = tid & 31;
    const int wm = wid & 1, wn = wid >> 1;
    const int lr = lane >> 2, lc = lane & 3;
    const int NC = K / 32;

#define B_LOAD_BT(buf, k0_) do {                                                 \
        int k0 = (k0_);                                                          \
        _Pragma("unroll")                                                        \
        for (int i = 0; i < 4; i++) {                                            \
            int id = tid + i * 128;                                              \
            int kk = id >> 4, n4 = (id & 15) * 4;                                \
            cp_async16(Bbuf[buf] + kk*BTPAD + n4,                                \
                       Wh + (size_t)(k0 + kk)*64 + n4);                          \
        }                                                                         \
    } while (0)

    A_LOAD(0, 0); B_LOAD_BT(0, 0); CP_COMMIT();
    A_LOAD(1, 32); B_LOAD_BT(1, 32); CP_COMMIT();

    float acc[4][4][4];
#pragma unroll
    for (int a = 0; a < 4; a++)
#pragma unroll
        for (int b = 0; b < 4; b++)
#pragma unroll
            for (int c = 0; c < 4; c++) acc[a][b][c] = 0.f;

    for (int c = 0; c < NC; c++) {
        if (c < NC - 1) CP_WAIT1(); else CP_WAIT0();
        __syncthreads();
        const int buf = c & 1;
        const float* Ab = Abuf[buf] + wm * 64 * GPAD;
        const float* Bb = Bbuf[buf];
#pragma unroll
        for (int ks = 0; ks < 4; ks++) {
            const int kb = ks * 8 + lc;
            uint32_t bh[4][2], bl[4][2];
#pragma unroll
            for (int nt = 0; nt < 4; nt++) {
                int nl = wn*32 + nt*8 + lr;
                splitf(Bb[kb*BTPAD + nl],       bh[nt][0], bl[nt][0]);
                splitf(Bb[(kb+4)*BTPAD + nl],   bh[nt][1], bl[nt][1]);
            }
#pragma unroll
            for (int mt = 0; mt < 4; mt++) {
                uint32_t ah[4], al[4];
                splitf(Ab[(mt*16 + lr    )*GPAD + kb],     ah[0], al[0]);
                splitf(Ab[(mt*16 + lr + 8)*GPAD + kb],     ah[1], al[1]);
                splitf(Ab[(mt*16 + lr    )*GPAD + kb + 4], ah[2], al[2]);
                splitf(Ab[(mt*16 + lr + 8)*GPAD + kb + 4], ah[3], al[3]);
#pragma unroll
                for (int nt = 0; nt < 4; nt++) {
                    mma8(acc[mt][nt], ah, bh[nt]);
                    mma8(acc[mt][nt], ah, bl[nt]);
                    mma8(acc[mt][nt], al, bh[nt]);
                }
            }
        }
        __syncthreads();
        if (c + 2 < NC) { A_LOAD(buf, (c + 2) * 32); B_LOAD_BT(buf, (c + 2) * 32); CP_COMMIT(); }
    }
    G_EPILOGUE()
#undef B_LOAD_BT
}

// ---- bf16 split 3-product core, B from W[h][d][e] as [k][n] tiles (V proj) ----
__device__ __forceinline__ void gemm_core_bf_bt(
    const float* __restrict__ A1, const float* __restrict__ Wh,
    float* __restrict__ C, int m0, int n0, float* sm)
{
    const float* A2 = A1; const int K1 = Dm, K = Dm;
    const float* bias = nullptr;
    float* Abuf[2] = { sm,              sm + 128*GPAD };
    float* Bbuf[2] = { sm + 2*128*GPAD, sm + 2*128*GPAD + 32*BTPAD };
    const int tid = threadIdx.x;
    const int wid = tid >> 5, lane = tid & 31;
    const int wm = wid & 1, wn = wid >> 1;
    const int lr = lane >> 2, lc = lane & 3;
    const int NC = K / 32;

#define B_LOAD_BT(buf, k0_) do {                                                 \
        int k0 = (k0_);                                                          \
        _Pragma("unroll")                                                        \
        for (int i = 0; i < 4; i++) {                                            \
            int id = tid + i * 128;                                              \
            int kk = id >> 4, n4 = (id & 15) * 4;                                \
            cp_async16(Bbuf[buf] + kk*BTPAD + n4,                                \
                       Wh + (size_t)(k0 + kk)*64 + n4);                          \
        }                                                                         \
    } while (0)

    A_LOAD(0, 0); B_LOAD_BT(0, 0); CP_COMMIT();
    A_LOAD(1, 32); B_LOAD_BT(1, 32); CP_COMMIT();

    float acc[4][4][4];
#pragma unroll
    for (int a = 0; a < 4; a++)
#pragma unroll
        for (int b = 0; b < 4; b++)
#pragma unroll
            for (int c = 0; c < 4; c++) acc[a][b][c] = 0.f;

    for (int c = 0; c < NC; c++) {
        if (c < NC - 1) CP_WAIT1(); else CP_WAIT0();
        __syncthreads();
        const int buf = c & 1;
        const float* Ab = Abuf[buf] + wm * 64 * GPAD;
        const float* Bb = Bbuf[buf];
#pragma unroll
        for (int ks = 0; ks < 2; ks++) {
            const int kb = ks * 16 + 2 * lc;
            uint32_t bh[4][2], bl[4][2];
#pragma unroll
            for (int nt = 0; nt < 4; nt++) {
                int nl = wn*32 + nt*8 + lr;
                split2(Bb[kb*BTPAD + nl],     Bb[(kb+1)*BTPAD + nl], bh[nt][0], bl[nt][0]);
                split2(Bb[(kb+8)*BTPAD + nl], Bb[(kb+9)*BTPAD + nl], bh[nt][1], bl[nt][1]);
            }
#pragma unroll
            for (int mt = 0; mt < 4; mt++) {
                uint32_t ah[4], al[4];
                float2 a00 = *(const float2*)(Ab + (mt*16 + lr    )*GPAD + kb);
                float2 a10 = *(const float2*)(Ab + (mt*16 + lr + 8)*GPAD + kb);
                float2 a01 = *(const float2*)(Ab + (mt*16 + lr    )*GPAD + kb + 8);
                float2 a11 = *(const float2*)(Ab + (mt*16 + lr + 8)*GPAD + kb + 8);
                split2(a00.x, a00.y, ah[0], al[0]);
                split2(a10.x, a10.y, ah[1], al[1]);
                split2(a01.x, a01.y, ah[2], al[2]);
                split2(a11.x, a11.y, ah[3], al[3]);
#pragma unroll
                for (int nt = 0; nt < 4; nt++) {
                    mma16(acc[mt][nt], ah, bh[nt]);
                    mma16(acc[mt][nt], ah, bl[nt]);
                    mma16(acc[mt][nt], al, bh[nt]);
                }
            }
        }
        __syncthreads();
        if (c + 2 < NC) { A_LOAD(buf, (c + 2) * 32); B_LOAD_BT(buf, (c + 2) * 32); CP_COMMIT(); }
    }
    G_EPILOGUE()
#undef B_LOAD_BT
}

// ---- bf16 split 3-product core, B = [n][k] row-major weights (proj/lin) ----
__device__ __forceinline__ void gemm_core_bf(
    const float* __restrict__ A1, const float* __restrict__ A2, int K1, int K,
    const float* __restrict__ Bm, const float* __restrict__ bias,
    float* __restrict__ C, int m0, int n0, float* sm)
{
    float* Abuf[2] = { sm,              sm + 128*GPAD };
    float* Bbuf[2] = { sm + 2*128*GPAD, sm + 2*128*GPAD + 64*GPAD };
    const int tid = threadIdx.x;
    const int wid = tid >> 5, lane = tid & 31;
    const int wm = wid & 1, wn = wid >> 1;
    const int lr = lane >> 2, lc = lane & 3;
    const int NC = K / 32;

#define B_LOAD_NK(buf, k0_) do {                                                 \
        int k0 = (k0_);                                                          \
        _Pragma("unroll")                                                        \
        for (int i = 0; i < 4; i++) {                                            \
            int id = tid + i * 128;                                              \
            int row = id >> 3, c4 = (id & 7) * 4;                                \
            cp_async16(Bbuf[buf] + row*GPAD + c4,                                \
                       Bm + (size_t)(n0 + row)*K + k0 + c4);                     \
        }                                                                         \
    } while (0)

    A_LOAD(0, 0); B_LOAD_NK(0, 0); CP_COMMIT();
    A_LOAD(1, 32); B_LOAD_NK(1, 32); CP_COMMIT();

    float acc[4][4][4];
#pragma unroll
    for (int a = 0; a < 4; a++)
#pragma unroll
        for (int b = 0; b < 4; b++)
#pragma unroll
            for (int c = 0; c < 4; c++) acc[a][b][c] = 0.f;

    for (int c = 0; c < NC; c++) {
        if (c < NC - 1) CP_WAIT1(); else CP_WAIT0();
        __syncthreads();
        const int buf = c & 1;
        const float* Ab = Abuf[buf] + wm * 64 * GPAD;
        const float* Bb = Bbuf[buf] + wn * 32 * GPAD;
#pragma unroll
        for (int ks = 0; ks < 2; ks++) {
            const int kb = ks * 16 + 2 * lc;
            uint32_t bh[4][2], bl[4][2];
#pragma unroll
            for (int nt = 0; nt < 4; nt++) {
                float2 b0 = *(const float2*)(Bb + (nt*8 + lr)*GPAD + kb);
                float2 b1 = *(const float2*)(Bb + (nt*8 + lr)*GPAD + kb + 8);
                split2(b0.x, b0.y, bh[nt][0], bl[nt][0]);
                split2(b1.x, b1.y, bh[nt][1], bl[nt][1]);
            }
#pragma unroll
            for (int mt = 0; mt < 4; mt++) {
                uint32_t ah[4], al[4];
                float2 a00 = *(const float2*)(Ab + (mt*16 + lr    )*GPAD + kb);
                float2 a10 = *(const float2*)(Ab + (mt*16 + lr + 8)*GPAD + kb);
                float2 a01 = *(const float2*)(Ab + (mt*16 + lr    )*GPAD + kb + 8);
                float2 a11 = *(const float2*)(Ab + (mt*16 + lr + 8)*GPAD + kb + 8);
                split2(a00.x, a00.y, ah[0], al[0]);
                split2(a10.x, a10.y, ah[1], al[1]);
                split2(a01.x, a01.y, ah[2], al[2]);
                split2(a11.x, a11.y, ah[3], al[3]);
#pragma unroll
                for (int nt = 0; nt < 4; nt++) {
                    mma16(acc[mt][nt], ah, bh[nt]);
                    mma16(acc[mt][nt], ah, bl[nt]);
                    mma16(acc[mt][nt], al, bh[nt]);
                }
            }
        }
        __syncthreads();
        if (c + 2 < NC) { A_LOAD(buf, (c + 2) * 32); B_LOAD_NK(buf, (c + 2) * 32); CP_COMMIT(); }
    }
    G_EPILOGUE()
#undef B_LOAD_NK
}

// Q/K projections (tf32, weights read in-place): z selects {q,k}; blockIdx.x = head
__global__ __launch_bounds__(128, 3) void qk_mma_bt(
    const float* __restrict__ qd, const float* __restrict__ kd,
    const float* __restrict__ wq, const float* __restrict__ wk)
{
    extern __shared__ float sm[];
    const int z = blockIdx.z;
    const float* A = (z == 0) ? qd : kd;
    const float* W = ((z == 0) ? wq : wk) + (size_t)blockIdx.x * Dm * 64;
    float* C = (z == 0) ? g_qs : g_ks;
    gemm_core_tf32_bt(A, W, C, blockIdx.y * 128, blockIdx.x * 64, sm);
}

// V projection (bf16, weights in-place)
__global__ __launch_bounds__(128, 3) void v_mma_bt(
    const float* __restrict__ vd, const float* __restrict__ wv)
{
    extern __shared__ float sm[];
    gemm_core_bf_bt(vd, wv + (size_t)blockIdx.x * Dm * 64, g_vs,
                    blockIdx.y * 128, blockIdx.x * 64, sm);
}

__global__ __launch_bounds__(128, 3) void gemm_bf_mma(
    const float* __restrict__ A1, const float* __restrict__ A2, int K1, int K,
    const float* __restrict__ Bm, const float* __restrict__ bias, float* __restrict__ C)
{
    extern __shared__ float sm[];
    gemm_core_bf(A1, A2, K1, K, Bm, bias, C, blockIdx.y * 128, blockIdx.x * 64, sm);
}

// ============================================================================
// QK^T + softmax stats + dense attn-output fill (zeros + scatter) fused.
// CTA = (h, b, 128 q rows); streams 16 K-tiles of 64 rows; raw-sum softmax
// (no online rescale; |s*CC| small), explicit max/argmax compare.
// ============================================================================
#define APAD 68
#define S_SMEM ((128*APAD + 2*64*APAD)*4 + 256*4*3)  /* 72704 */
__global__ __launch_bounds__(128, 3) void attn_stats_mma(float* __restrict__ attn)
{
    extern __shared__ float sm[];
    float* Qs   = sm;
    float* Kbuf[2] = { sm + 128*APAD, sm + 128*APAD + 64*APAD };
    float* redm = sm + 128*APAD + 2*64*APAD;
    float* reds = redm + 256;
    int*   redi = (int*)(reds + 256);

    const int tid = threadIdx.x;
    const int h = blockIdx.z, b = blockIdx.y, q0 = blockIdx.x * 128;
    const int wid = tid >> 5, lane = tid & 31;
    const int wm = wid & 1, wn = wid >> 1;
    const int lr = lane >> 2, lc = lane & 3;

    const float* Qg = g_qs + ((size_t)(b * Ls + q0)) * Dm + h * 64;
    const float* Kg = g_ks + ((size_t)(b * Ls)) * Dm + h * 64;
    const size_t rowbase = (size_t)(h * Bn + b) * Ls + q0;   // attn row base

#pragma unroll
    for (int i = 0; i < 16; i++) {
        int id = tid + i * 128;
        int row = id >> 4, c4 = (id & 15) * 4;
        cp_async16(Qs + row*APAD + c4, Qg + (size_t)row * Dm + c4);
    }
    CP_COMMIT();

#define K_LOAD(buf, t_) do {                                                    \
        _Pragma("unroll")                                                       \
        for (int i = 0; i < 8; i++) {                                           \
            int id = tid + i * 128;                                             \
            int row = id >> 4, c4 = (id & 15) * 4;                              \
            cp_async16(Kbuf[buf] + row*APAD + c4,                               \
                       Kg + (size_t)((t_)*64 + row) * Dm + c4);                 \
        }                                                                       \
    } while (0)

    K_LOAD(0, 0); CP_COMMIT();
    K_LOAD(1, 1); CP_COMMIT();

    float rm[8], rs[8];
    int ridx[8];
#pragma unroll
    for (int i = 0; i < 8; i++) { rm[i] = -1e30f; rs[i] = 0.f; ridx[i] = 0; }

    for (int t = 0; t < 16; t++) {
        if (t < 15) CP_WAIT1(); else CP_WAIT0();
        __syncthreads();
        const int buf = t & 1;
        const float* Ab = Qs + wm * 64 * APAD;
        const float* Bb = Kbuf[buf] + wn * 32 * APAD;

        float acc[4][4][4];
#pragma unroll
        for (int a = 0; a < 4; a++)
#pragma unroll
            for (int bb = 0; bb < 4; bb++)
#pragma unroll
                for (int cc = 0; cc < 4; cc++) acc[a][bb][cc] = 0.f;

#pragma unroll
        for (int ks = 0; ks < 8; ks++) {
            const int kb = ks * 8 + lc;
            uint32_t bh[4][2], bl[4][2];
#pragma unroll
            for (int nt = 0; nt < 4; nt++) {
                splitf(Bb[(nt*8 + lr)*APAD + kb],     bh[nt][0], bl[nt][0]);
                splitf(Bb[(nt*8 + lr)*APAD + kb + 4], bh[nt][1], bl[nt][1]);
            }
#pragma unroll
            for (int mt = 0; mt < 4; mt++) {
                uint32_t ah[4], al[4];
                splitf(Ab[(mt*16 + lr    )*APAD + kb],     ah[0], al[0]);
                splitf(Ab[(mt*16 + lr + 8)*APAD + kb],     ah[1], al[1]);
                splitf(Ab[(mt*16 + lr    )*APAD + kb + 4], ah[2], al[2]);
                splitf(Ab[(mt*16 + lr + 8)*APAD + kb + 4], ah[3], al[3]);
#pragma unroll
                for (int nt = 0; nt < 4; nt++) {
                    mma8(acc[mt][nt], ah, bh[nt]);
                    mma8(acc[mt][nt], ah, bl[nt]);
                    mma8(acc[mt][nt], al, bh[nt]);
                }
            }
        }

        // streaming zero-fill of this CTA's attn slice, s-range [t*64, t*64+64)
        {
            float4 z4 = make_float4(0.f, 0.f, 0.f, 0.f);
#pragma unroll
            for (int i = 0; i < 16; i++) {
                int id = tid + i * 128;
                int r = id >> 4, f4 = id & 15;
                __stcs((float4*)(attn + (rowbase + r) * Ls + t * 64 + f4 * 4), z4);
            }
        }

        // fold tile into per-thread stats (raw sum + explicit max/argmax)
        const int sbase = t * 64 + wn * 32 + 2 * lc;
#pragma unroll
        for (int mt = 0; mt < 4; mt++) {
#pragma unroll
            for (int half = 0; half < 2; half++) {
                const int r8 = mt * 2 + half;
                float m = rm[r8], s_ = rs[r8];
                int id_ = ridx[r8];
#pragma unroll
                for (int nt = 0; nt < 4; nt++) {
#pragma unroll
                    for (int j = 0; j < 2; j++) {
                        float v = acc[mt][nt][half*2 + j];
                        if (v > m) { m = v; id_ = sbase + nt*8 + j; }
                        s_ += fexp2s(v * CC);
                    }
                }
                rm[r8] = m; rs[r8] = s_; ridx[r8] = id_;
            }
        }
        __syncthreads();
        if (t + 2 < 16) { K_LOAD(buf, t + 2); CP_COMMIT(); }
    }

    // quad reduce over lc (same rows, different cols)
#pragma unroll
    for (int r8 = 0; r8 < 8; r8++) {
        float m = rm[r8], s_ = rs[r8];
        int id_ = ridx[r8];
#pragma unroll
        for (int off = 1; off <= 2; off <<= 1) {
            float om = __shfl_xor_sync(0xffffffffu, m, off);
            float os = __shfl_xor_sync(0xffffffffu, s_, off);
            int   oi = __shfl_xor_sync(0xffffffffu, id_, off);
            s_ += os;
            if (om > m) { m = om; id_ = oi; }
        }
        if (lc == 0) {
            int rowl = wm*64 + (r8 >> 1)*16 + (r8 & 1)*8 + lr;
            redm[rowl*2 + wn] = m;
            reds[rowl*2 + wn] = s_;
            redi[rowl*2 + wn] = id_;
        }
    }
    __syncthreads();   // also orders all zero-fill stores before the scatter below

    {
        float m = redm[tid*2], s_ = reds[tid*2];
        int id_ = redi[tid*2];
        float om = redm[tid*2 + 1];
        s_ += reds[tid*2 + 1];
        if (om > m) { m = om; id_ = redi[tid*2 + 1]; }
        float p = fexp2s(m * CC) / s_;
        int row = (int)(rowbase) + tid;
        g_p[row] = p;
        g_amax[row] = id_;
        attn[(rowbase + tid) * Ls + id_] = p;     // scatter the single nonzero
    }
#undef K_LOAD
}

// ============================================================================
// attn @ V collapsed to a vectorized gather
// ============================================================================
__global__ void gather_kernel()
{
    int idx4 = blockIdx.x * blockDim.x + threadIdx.x;   // over M_ALL*Dm/4
    if (idx4 >= M_ALL * Dm / 4) return;
    int e4 = idx4 & 15;            // 16 float4 per head
    int h  = (idx4 >> 4) & 7;
    int m  = idx4 >> 7;            // b*L + q
    int b  = m >> 10;
    int q  = m & 1023;
    int row = (h * Bn + b) * Ls + q;
    float p = g_p[row];
    int   s = g_amax[row];
    float4 v = *(const float4*)(g_vs + ((size_t)(b * Ls + s)) * Dm + h * 64 + e4 * 4);
    v.x *= p; v.y *= p; v.z *= p; v.w *= p;
    *(float4*)(g_headout + (size_t)idx4 * 4) = v;
}

// ============================================================================
extern "C" void kernel_launch(void* const* d_in, const int* in_sizes, int n_in,
                              void* d_out, int out_size)
{
    const float* q_data = (const float*)d_in[0];
    const float* k_data = (const float*)d_in[1];
    const float* v_data = (const float*)d_in[2];
    const float* w_qs   = (const float*)d_in[3];
    const float* w_ks   = (const float*)d_in[4];
    const float* w_vs   = (const float*)d_in[5];
    const float* proj_w = (const float*)d_in[6];
    const float* proj_b = (const float*)d_in[7];
    const float* lin_w  = (const float*)d_in[8];
    const float* lin_b  = (const float*)d_in[9];

    float* out  = (float*)d_out;                    // [B, L, D]
    float* attn = out + OUT_ELEMS;                  // [H*B, L, L]

    float *p_ho, *p_po;
    cudaGetSymbolAddress((void**)&p_ho, g_headout);
    cudaGetSymbolAddress((void**)&p_po, g_projout);

    cudaFuncSetAttribute(qk_mma_bt,  cudaFuncAttributeMaxDynamicSharedMemorySize, G_SMEM_BT);
    cudaFuncSetAttribute(v_mma_bt,   cudaFuncAttributeMaxDynamicSharedMemorySize, G_SMEM_BT);
    cudaFuncSetAttribute(gemm_bf_mma, cudaFuncAttributeMaxDynamicSharedMemorySize, G_SMEM);
    cudaFuncSetAttribute(attn_stats_mma, cudaFuncAttributeMaxDynamicSharedMemorySize, S_SMEM);

    // 1) Q/K projections (tf32 3-product, weights read in-place)
    qk_mma_bt<<<dim3(8, 128, 2), 128, G_SMEM_BT>>>(q_data, k_data, w_qs, w_ks);

    // 1b) V projection (bf16 split 3-product, weights in-place)
    v_mma_bt<<<dim3(8, 128), 128, G_SMEM_BT>>>(v_data, w_vs);

    // 2) QK^T + softmax stats + full dense attn-output fill (fused)
    attn_stats_mma<<<dim3(8, 16, 8), 128, S_SMEM>>>(attn);

    // 3) attn @ V collapsed to gather (vectorized)
    gather_kernel<<<(M_ALL * Dm / 4 + 255) / 256, 256>>>();

    // 4) output projection (bf16)
    gemm_bf_mma<<<dim3(8, 128), 128, G_SMEM>>>(p_ho, p_ho, Dm, Dm, proj_w, proj_b, p_po);

    // 5) final linear (bf16): out = [q_data | projout] @ lin_w^T + lin_b
    gemm_bf_mma<<<dim3(8, 128), 128, G_SMEM>>>(q_data, p_po, Dm, 2*Dm, lin_w, lin_b, out);
}